// round 1
// baseline (speedup 1.0000x reference)
#include <cuda_runtime.h>
#include <math.h>

#define T_TOKENS 4096
#define DIMD     1024
#define INTER    1408
#define SINTER   2816
#define NEXP     16

// ---------------- device scratch (no allocations allowed) ----------------
__device__ int   g_cnt[NEXP];
__device__ int   g_off[NEXP];
__device__ int   g_tok[NEXP * T_TOKENS];
__device__ float g_wt [NEXP * T_TOKENS];
__device__ int   g_se [T_TOKENS * 2];   // expert id per (token, slot)
__device__ int   g_sp [T_TOKENS * 2];   // position within expert list
__device__ float g_sw [T_TOKENS * 2];   // routing weight
__device__ float g_act[T_TOKENS * 2 * INTER];   // 46.1 MB routed SwiGLU activations (compact rows)
__device__ float g_y  [T_TOKENS * 2 * DIMD];    // 33.6 MB routed down-proj outputs
__device__ float g_z  [T_TOKENS * SINTER];      // 46.1 MB shared SwiGLU activations

// ---------------- reset (graph replays reuse state) ----------------
__global__ void reset_kernel() {
    if (threadIdx.x < NEXP) g_cnt[threadIdx.x] = 0;
}

// ---------------- gate: logits -> softmax -> top2 -> expert lists ----------------
__global__ void gate_kernel(const float* __restrict__ x,
                            const float* __restrict__ gw,
                            const float* __restrict__ gb)
{
    int t = blockIdx.x * blockDim.y + threadIdx.y;
    if (t >= T_TOKENS) return;
    int lane = threadIdx.x;

    float acc[NEXP];
#pragma unroll
    for (int e = 0; e < NEXP; e++) acc[e] = 0.f;

    const float* xr = x + (size_t)t * DIMD;
    for (int d = lane; d < DIMD; d += 32) {
        float xv = xr[d];
        const float* g = gw + (size_t)d * NEXP;
#pragma unroll
        for (int e = 0; e < NEXP; e++) acc[e] += xv * g[e];
    }
#pragma unroll
    for (int e = 0; e < NEXP; e++) {
#pragma unroll
        for (int o = 16; o > 0; o >>= 1)
            acc[e] += __shfl_xor_sync(0xffffffffu, acc[e], o);
    }
    if (lane == 0) {
        float mx = -1e30f;
#pragma unroll
        for (int e = 0; e < NEXP; e++) { acc[e] += gb[e]; mx = fmaxf(mx, acc[e]); }
        float s = 0.f;
#pragma unroll
        for (int e = 0; e < NEXP; e++) { acc[e] = expf(acc[e] - mx); s += acc[e]; }

        int b0 = 0; float v0 = -1.f;
#pragma unroll
        for (int e = 0; e < NEXP; e++) if (acc[e] > v0) { v0 = acc[e]; b0 = e; }
        int b1i = -1; float v1 = -1.f;
#pragma unroll
        for (int e = 0; e < NEXP; e++) if (e != b0 && acc[e] > v1) { v1 = acc[e]; b1i = e; }

        float w0 = v0 / s;
        float w1 = v1 / s;

        int p0 = atomicAdd(&g_cnt[b0], 1);
        g_tok[b0 * T_TOKENS + p0] = t;
        g_wt [b0 * T_TOKENS + p0] = w0;
        int p1 = atomicAdd(&g_cnt[b1i], 1);
        g_tok[b1i * T_TOKENS + p1] = t;
        g_wt [b1i * T_TOKENS + p1] = w1;

        g_se[t * 2 + 0] = b0;  g_sp[t * 2 + 0] = p0;  g_sw[t * 2 + 0] = w0;
        g_se[t * 2 + 1] = b1i; g_sp[t * 2 + 1] = p1;  g_sw[t * 2 + 1] = w1;
    }
}

__global__ void scan_kernel() {
    int s = 0;
    for (int e = 0; e < NEXP; e++) { g_off[e] = s; s += g_cnt[e]; }
}

// ---------------- fused up-projection (W1 & W3) + SwiGLU ----------------
// BM=128, BN=64, BK=16, 256 threads, per-thread 8x4 for H and G.
// GATHER=true  -> routed: gathered token rows, expert weights, writes g_act (compact)
// GATHER=false -> shared expert over all tokens, writes g_z
template<int NN, bool GATHER>
__global__ void __launch_bounds__(256)
up_kernel(const float* __restrict__ x,
          const float* __restrict__ w1g, const float* __restrict__ b1g,
          const float* __restrict__ w3g, const float* __restrict__ b3g)
{
    const int n0 = blockIdx.x * 64;
    const int m0 = blockIdx.y * 128;
    int M = T_TOKENS, rowbase = 0, e = 0;
    const float* w1 = w1g; const float* w3 = w3g;
    const float* b1 = b1g; const float* b3 = b3g;
    if (GATHER) {
        e = blockIdx.z;
        M = g_cnt[e];
        if (m0 >= M) return;
        rowbase = g_off[e];
        w1 += (size_t)e * DIMD * NN;
        w3 += (size_t)e * DIMD * NN;
        b1 += (size_t)e * NN;
        b3 += (size_t)e * NN;
    }
    float* outp = GATHER ? g_act : g_z;

    __shared__ float Xs [16][132];
    __shared__ float W1s[16][68];
    __shared__ float W3s[16][68];

    const int tid = threadIdx.x;
    const int lm  = tid >> 1;          // A-load row 0..127
    const int lk4 = (tid & 1) * 2;     // which pair of float4s in the row

    const float* xrow = nullptr;
    {
        int r = m0 + lm;
        if (r < M) {
            int tok = GATHER ? g_tok[e * T_TOKENS + r] : r;
            xrow = x + (size_t)tok * DIMD;
        }
    }
    const int bk = tid >> 4;
    const int bn = (tid & 15) << 2;

    float accH[8][4], accG[8][4];
#pragma unroll
    for (int i = 0; i < 8; i++)
#pragma unroll
        for (int j = 0; j < 4; j++) { accH[i][j] = 0.f; accG[i][j] = 0.f; }

    const int ty = tid >> 4, tx = tid & 15;

    for (int k0 = 0; k0 < DIMD; k0 += 16) {
#pragma unroll
        for (int q = 0; q < 2; q++) {
            float4 v = xrow ? *(const float4*)(xrow + k0 + ((lk4 + q) << 2))
                            : make_float4(0.f, 0.f, 0.f, 0.f);
            int kk = (lk4 + q) << 2;
            Xs[kk + 0][lm] = v.x; Xs[kk + 1][lm] = v.y;
            Xs[kk + 2][lm] = v.z; Xs[kk + 3][lm] = v.w;
        }
        *(float4*)&W1s[bk][bn] = *(const float4*)(w1 + (size_t)(k0 + bk) * NN + n0 + bn);
        *(float4*)&W3s[bk][bn] = *(const float4*)(w3 + (size_t)(k0 + bk) * NN + n0 + bn);
        __syncthreads();
#pragma unroll
        for (int k = 0; k < 16; k++) {
            float a[8], p1[4], p3[4];
#pragma unroll
            for (int i = 0; i < 8; i++) a[i] = Xs[k][ty * 8 + i];
#pragma unroll
            for (int j = 0; j < 4; j++) { p1[j] = W1s[k][tx * 4 + j]; p3[j] = W3s[k][tx * 4 + j]; }
#pragma unroll
            for (int i = 0; i < 8; i++)
#pragma unroll
                for (int j = 0; j < 4; j++) {
                    accH[i][j] = fmaf(a[i], p1[j], accH[i][j]);
                    accG[i][j] = fmaf(a[i], p3[j], accG[i][j]);
                }
        }
        __syncthreads();
    }

#pragma unroll
    for (int i = 0; i < 8; i++) {
        int r = m0 + ty * 8 + i;
        if (r >= M) continue;
        float wgt = GATHER ? g_wt[e * T_TOKENS + r] : 1.f;
        int n = n0 + tx * 4;
        float res[4];
#pragma unroll
        for (int j = 0; j < 4; j++) {
            float h = accH[i][j] + b1[n + j];
            float g = accG[i][j] + b3[n + j];
            float sil = h / (1.f + __expf(-h));
            res[j] = sil * g * wgt;
        }
        float* orow = outp + (size_t)(rowbase + r) * NN + n;
        *(float4*)orow = make_float4(res[0], res[1], res[2], res[3]);
    }
}

// ---------------- down-projection ----------------
// ROUTED=true  -> g_act[M,1408] @ w2[e] -> g_y (weights already folded into g_act)
// ROUTED=false -> g_z[4096,2816] @ sw2 + sb2 -> out (covers every element once)
template<int KK, bool ROUTED>
__global__ void __launch_bounds__(256)
down_kernel(const float* __restrict__ w2g,
            const float* __restrict__ bias,
            float* __restrict__ out_arg)
{
    const int n0 = blockIdx.x * 64;
    const int m0 = blockIdx.y * 128;
    int M = T_TOKENS, rowbase = 0;
    const float* w2 = w2g;
    if (ROUTED) {
        int e = blockIdx.z;
        M = g_cnt[e];
        if (m0 >= M) return;
        rowbase = g_off[e];
        w2 += (size_t)e * KK * DIMD;
    }
    const float* Ain = ROUTED ? g_act : g_z;
    float* outp = ROUTED ? g_y : out_arg;

    __shared__ float As[16][132];
    __shared__ float Ws[16][68];

    const int tid = threadIdx.x;
    const int lm  = tid >> 1;
    const int lk4 = (tid & 1) * 2;
    const float* arow = nullptr;
    {
        int r = m0 + lm;
        if (r < M) arow = Ain + (size_t)(rowbase + r) * KK;
    }
    const int bk = tid >> 4, bn = (tid & 15) << 2;

    float acc[8][4];
#pragma unroll
    for (int i = 0; i < 8; i++)
#pragma unroll
        for (int j = 0; j < 4; j++) acc[i][j] = 0.f;

    const int ty = tid >> 4, tx = tid & 15;

    for (int k0 = 0; k0 < KK; k0 += 16) {
#pragma unroll
        for (int q = 0; q < 2; q++) {
            float4 v = arow ? *(const float4*)(arow + k0 + ((lk4 + q) << 2))
                            : make_float4(0.f, 0.f, 0.f, 0.f);
            int kk = (lk4 + q) << 2;
            As[kk + 0][lm] = v.x; As[kk + 1][lm] = v.y;
            As[kk + 2][lm] = v.z; As[kk + 3][lm] = v.w;
        }
        *(float4*)&Ws[bk][bn] = *(const float4*)(w2 + (size_t)(k0 + bk) * DIMD + n0 + bn);
        __syncthreads();
#pragma unroll
        for (int k = 0; k < 16; k++) {
            float a[8], b[4];
#pragma unroll
            for (int i = 0; i < 8; i++) a[i] = As[k][ty * 8 + i];
#pragma unroll
            for (int j = 0; j < 4; j++) b[j] = Ws[k][tx * 4 + j];
#pragma unroll
            for (int i = 0; i < 8; i++)
#pragma unroll
                for (int j = 0; j < 4; j++)
                    acc[i][j] = fmaf(a[i], b[j], acc[i][j]);
        }
        __syncthreads();
    }

#pragma unroll
    for (int i = 0; i < 8; i++) {
        int r = m0 + ty * 8 + i;
        if (r >= M) continue;
        int n = n0 + tx * 4;
        float res[4];
#pragma unroll
        for (int j = 0; j < 4; j++)
            res[j] = ROUTED ? acc[i][j] : (acc[i][j] + bias[n + j]);
        float* orow = outp + (size_t)(rowbase + r) * DIMD + n;
        *(float4*)orow = make_float4(res[0], res[1], res[2], res[3]);
    }
}

// ---------------- combine: out += routed contributions + cw@b2 ----------------
__global__ void combine_kernel(const float* __restrict__ b2, float* __restrict__ out)
{
    int t = blockIdx.x;
    int d = threadIdx.x * 4;
    int e0 = g_se[t * 2 + 0], e1 = g_se[t * 2 + 1];
    int r0 = g_off[e0] + g_sp[t * 2 + 0];
    int r1 = g_off[e1] + g_sp[t * 2 + 1];
    float w0 = g_sw[t * 2 + 0], w1 = g_sw[t * 2 + 1];

    float4 y0  = *(const float4*)&g_y[(size_t)r0 * DIMD + d];
    float4 y1  = *(const float4*)&g_y[(size_t)r1 * DIMD + d];
    float4 bb0 = *(const float4*)&b2[(size_t)e0 * DIMD + d];
    float4 bb1 = *(const float4*)&b2[(size_t)e1 * DIMD + d];

    float4* o = (float4*)&out[(size_t)t * DIMD + d];
    float4 c = *o;
    c.x += y0.x + y1.x + w0 * bb0.x + w1 * bb1.x;
    c.y += y0.y + y1.y + w0 * bb0.y + w1 * bb1.y;
    c.z += y0.z + y1.z + w0 * bb0.z + w1 * bb1.z;
    c.w += y0.w + y1.w + w0 * bb0.w + w1 * bb1.w;
    *o = c;
}

// ---------------- launch ----------------
extern "C" void kernel_launch(void* const* d_in, const int* in_sizes, int n_in,
                              void* d_out, int out_size)
{
    const float* x   = (const float*)d_in[0];
    const float* gw  = (const float*)d_in[1];
    const float* gb  = (const float*)d_in[2];
    const float* w1  = (const float*)d_in[3];
    const float* b1  = (const float*)d_in[4];
    const float* w3  = (const float*)d_in[5];
    const float* b3  = (const float*)d_in[6];
    const float* w2  = (const float*)d_in[7];
    const float* b2  = (const float*)d_in[8];
    const float* sw1 = (const float*)d_in[9];
    const float* sb1 = (const float*)d_in[10];
    const float* sw3 = (const float*)d_in[11];
    const float* sb3 = (const float*)d_in[12];
    const float* sw2 = (const float*)d_in[13];
    const float* sb2 = (const float*)d_in[14];
    float* out = (float*)d_out;

    reset_kernel<<<1, 32>>>();
    gate_kernel<<<T_TOKENS / 4, dim3(32, 4)>>>(x, gw, gb);
    scan_kernel<<<1, 1>>>();

    // shared expert path
    up_kernel<SINTER, false><<<dim3(SINTER / 64, T_TOKENS / 128), 256>>>(x, sw1, sb1, sw3, sb3);
    down_kernel<SINTER, false><<<dim3(DIMD / 64, T_TOKENS / 128), 256>>>(sw2, sb2, out);

    // routed expert path (early-exit grid over max tiles)
    up_kernel<INTER, true><<<dim3(INTER / 64, T_TOKENS / 128, NEXP), 256>>>(x, w1, b1, w3, b3);
    down_kernel<INTER, true><<<dim3(DIMD / 64, T_TOKENS / 128, NEXP), 256>>>(w2, nullptr, nullptr);

    combine_kernel<<<T_TOKENS, 256>>>(b2, out);
}

// round 2
// speedup vs baseline: 1.0000x; 1.0000x over previous
#include <cuda_runtime.h>
#include <math.h>

#define T_TOKENS 4096
#define DIMD     1024
#define INTER    1408
#define SINTER   2816
#define NEXP     16

// ---------------- device scratch (no allocations allowed) ----------------
__device__ int   g_cnt[NEXP];
__device__ int   g_off[NEXP];
__device__ int   g_tok[NEXP * T_TOKENS];
__device__ float g_wt [NEXP * T_TOKENS];
__device__ int   g_se [T_TOKENS * 2];   // expert id per (token, slot)
__device__ int   g_sp [T_TOKENS * 2];   // position within expert list
__device__ float g_sw [T_TOKENS * 2];   // routing weight
__device__ float g_act[T_TOKENS * 2 * INTER];   // 46.1 MB routed SwiGLU activations (compact rows)
__device__ float g_y  [T_TOKENS * 2 * DIMD];    // 33.6 MB routed down-proj outputs
__device__ float g_z  [T_TOKENS * SINTER];      // 46.1 MB shared SwiGLU activations

// ---------------- reset (graph replays reuse state) ----------------
__global__ void reset_kernel() {
    if (threadIdx.x < NEXP) g_cnt[threadIdx.x] = 0;
}

// ---------------- gate: logits -> softmax -> top2 -> expert lists ----------------
__global__ void gate_kernel(const float* __restrict__ x,
                            const float* __restrict__ gw,
                            const float* __restrict__ gb)
{
    int t = blockIdx.x * blockDim.y + threadIdx.y;
    if (t >= T_TOKENS) return;
    int lane = threadIdx.x;

    float acc[NEXP];
#pragma unroll
    for (int e = 0; e < NEXP; e++) acc[e] = 0.f;

    const float* xr = x + (size_t)t * DIMD;
    for (int d = lane; d < DIMD; d += 32) {
        float xv = xr[d];
        const float* g = gw + (size_t)d * NEXP;
#pragma unroll
        for (int e = 0; e < NEXP; e++) acc[e] += xv * g[e];
    }
#pragma unroll
    for (int e = 0; e < NEXP; e++) {
#pragma unroll
        for (int o = 16; o > 0; o >>= 1)
            acc[e] += __shfl_xor_sync(0xffffffffu, acc[e], o);
    }
    if (lane == 0) {
        float mx = -1e30f;
#pragma unroll
        for (int e = 0; e < NEXP; e++) { acc[e] += gb[e]; mx = fmaxf(mx, acc[e]); }
        float s = 0.f;
#pragma unroll
        for (int e = 0; e < NEXP; e++) { acc[e] = expf(acc[e] - mx); s += acc[e]; }

        int b0 = 0; float v0 = -1.f;
#pragma unroll
        for (int e = 0; e < NEXP; e++) if (acc[e] > v0) { v0 = acc[e]; b0 = e; }
        int b1i = -1; float v1 = -1.f;
#pragma unroll
        for (int e = 0; e < NEXP; e++) if (e != b0 && acc[e] > v1) { v1 = acc[e]; b1i = e; }

        float w0 = v0 / s;
        float w1 = v1 / s;

        int p0 = atomicAdd(&g_cnt[b0], 1);
        g_tok[b0 * T_TOKENS + p0] = t;
        g_wt [b0 * T_TOKENS + p0] = w0;
        int p1 = atomicAdd(&g_cnt[b1i], 1);
        g_tok[b1i * T_TOKENS + p1] = t;
        g_wt [b1i * T_TOKENS + p1] = w1;

        g_se[t * 2 + 0] = b0;  g_sp[t * 2 + 0] = p0;  g_sw[t * 2 + 0] = w0;
        g_se[t * 2 + 1] = b1i; g_sp[t * 2 + 1] = p1;  g_sw[t * 2 + 1] = w1;
    }
}

__global__ void scan_kernel() {
    int s = 0;
    for (int e = 0; e < NEXP; e++) { g_off[e] = s; s += g_cnt[e]; }
}

// ---------------- fused up-projection (W1 & W3) + SwiGLU ----------------
// BM=128, BN=64, BK=16, 256 threads, per-thread 8x4 for H and G.
// GATHER=true  -> routed: gathered token rows, expert weights, writes g_act (compact)
// GATHER=false -> shared expert over all tokens, writes g_z
template<int NN, bool GATHER>
__global__ void __launch_bounds__(256)
up_kernel(const float* __restrict__ x,
          const float* __restrict__ w1g, const float* __restrict__ b1g,
          const float* __restrict__ w3g, const float* __restrict__ b3g)
{
    const int n0 = blockIdx.x * 64;
    const int m0 = blockIdx.y * 128;
    int M = T_TOKENS, rowbase = 0, e = 0;
    const float* w1 = w1g; const float* w3 = w3g;
    const float* b1 = b1g; const float* b3 = b3g;
    if (GATHER) {
        e = blockIdx.z;
        M = g_cnt[e];
        if (m0 >= M) return;
        rowbase = g_off[e];
        w1 += (size_t)e * DIMD * NN;
        w3 += (size_t)e * DIMD * NN;
        b1 += (size_t)e * NN;
        b3 += (size_t)e * NN;
    }
    float* outp = GATHER ? g_act : g_z;

    __shared__ float Xs [16][132];
    __shared__ float W1s[16][68];
    __shared__ float W3s[16][68];

    const int tid = threadIdx.x;
    const int lm  = tid >> 1;          // A-load row 0..127
    const int lk4 = (tid & 1) * 2;     // which pair of float4s in the row

    const float* xrow = nullptr;
    {
        int r = m0 + lm;
        if (r < M) {
            int tok = GATHER ? g_tok[e * T_TOKENS + r] : r;
            xrow = x + (size_t)tok * DIMD;
        }
    }
    const int bk = tid >> 4;
    const int bn = (tid & 15) << 2;

    float accH[8][4], accG[8][4];
#pragma unroll
    for (int i = 0; i < 8; i++)
#pragma unroll
        for (int j = 0; j < 4; j++) { accH[i][j] = 0.f; accG[i][j] = 0.f; }

    const int ty = tid >> 4, tx = tid & 15;

    for (int k0 = 0; k0 < DIMD; k0 += 16) {
#pragma unroll
        for (int q = 0; q < 2; q++) {
            float4 v = xrow ? *(const float4*)(xrow + k0 + ((lk4 + q) << 2))
                            : make_float4(0.f, 0.f, 0.f, 0.f);
            int kk = (lk4 + q) << 2;
            Xs[kk + 0][lm] = v.x; Xs[kk + 1][lm] = v.y;
            Xs[kk + 2][lm] = v.z; Xs[kk + 3][lm] = v.w;
        }
        *(float4*)&W1s[bk][bn] = *(const float4*)(w1 + (size_t)(k0 + bk) * NN + n0 + bn);
        *(float4*)&W3s[bk][bn] = *(const float4*)(w3 + (size_t)(k0 + bk) * NN + n0 + bn);
        __syncthreads();
#pragma unroll
        for (int k = 0; k < 16; k++) {
            float a[8], p1[4], p3[4];
#pragma unroll
            for (int i = 0; i < 8; i++) a[i] = Xs[k][ty * 8 + i];
#pragma unroll
            for (int j = 0; j < 4; j++) { p1[j] = W1s[k][tx * 4 + j]; p3[j] = W3s[k][tx * 4 + j]; }
#pragma unroll
            for (int i = 0; i < 8; i++)
#pragma unroll
                for (int j = 0; j < 4; j++) {
                    accH[i][j] = fmaf(a[i], p1[j], accH[i][j]);
                    accG[i][j] = fmaf(a[i], p3[j], accG[i][j]);
                }
        }
        __syncthreads();
    }

#pragma unroll
    for (int i = 0; i < 8; i++) {
        int r = m0 + ty * 8 + i;
        if (r >= M) continue;
        float wgt = GATHER ? g_wt[e * T_TOKENS + r] : 1.f;
        int n = n0 + tx * 4;
        float res[4];
#pragma unroll
        for (int j = 0; j < 4; j++) {
            float h = accH[i][j] + b1[n + j];
            float g = accG[i][j] + b3[n + j];
            float sil = h / (1.f + __expf(-h));
            res[j] = sil * g * wgt;
        }
        float* orow = outp + (size_t)(rowbase + r) * NN + n;
        *(float4*)orow = make_float4(res[0], res[1], res[2], res[3]);
    }
}

// ---------------- down-projection ----------------
// ROUTED=true  -> g_act[M,1408] @ w2[e] -> g_y (weights already folded into g_act)
// ROUTED=false -> g_z[4096,2816] @ sw2 + sb2 -> out (covers every element once)
template<int KK, bool ROUTED>
__global__ void __launch_bounds__(256)
down_kernel(const float* __restrict__ w2g,
            const float* __restrict__ bias,
            float* __restrict__ out_arg)
{
    const int n0 = blockIdx.x * 64;
    const int m0 = blockIdx.y * 128;
    int M = T_TOKENS, rowbase = 0;
    const float* w2 = w2g;
    if (ROUTED) {
        int e = blockIdx.z;
        M = g_cnt[e];
        if (m0 >= M) return;
        rowbase = g_off[e];
        w2 += (size_t)e * KK * DIMD;
    }
    const float* Ain = ROUTED ? g_act : g_z;
    float* outp = ROUTED ? g_y : out_arg;

    __shared__ float As[16][132];
    __shared__ float Ws[16][68];

    const int tid = threadIdx.x;
    const int lm  = tid >> 1;
    const int lk4 = (tid & 1) * 2;
    const float* arow = nullptr;
    {
        int r = m0 + lm;
        if (r < M) arow = Ain + (size_t)(rowbase + r) * KK;
    }
    const int bk = tid >> 4, bn = (tid & 15) << 2;

    float acc[8][4];
#pragma unroll
    for (int i = 0; i < 8; i++)
#pragma unroll
        for (int j = 0; j < 4; j++) acc[i][j] = 0.f;

    const int ty = tid >> 4, tx = tid & 15;

    for (int k0 = 0; k0 < KK; k0 += 16) {
#pragma unroll
        for (int q = 0; q < 2; q++) {
            float4 v = arow ? *(const float4*)(arow + k0 + ((lk4 + q) << 2))
                            : make_float4(0.f, 0.f, 0.f, 0.f);
            int kk = (lk4 + q) << 2;
            As[kk + 0][lm] = v.x; As[kk + 1][lm] = v.y;
            As[kk + 2][lm] = v.z; As[kk + 3][lm] = v.w;
        }
        *(float4*)&Ws[bk][bn] = *(const float4*)(w2 + (size_t)(k0 + bk) * DIMD + n0 + bn);
        __syncthreads();
#pragma unroll
        for (int k = 0; k < 16; k++) {
            float a[8], b[4];
#pragma unroll
            for (int i = 0; i < 8; i++) a[i] = As[k][ty * 8 + i];
#pragma unroll
            for (int j = 0; j < 4; j++) b[j] = Ws[k][tx * 4 + j];
#pragma unroll
            for (int i = 0; i < 8; i++)
#pragma unroll
                for (int j = 0; j < 4; j++)
                    acc[i][j] = fmaf(a[i], b[j], acc[i][j]);
        }
        __syncthreads();
    }

#pragma unroll
    for (int i = 0; i < 8; i++) {
        int r = m0 + ty * 8 + i;
        if (r >= M) continue;
        int n = n0 + tx * 4;
        float res[4];
#pragma unroll
        for (int j = 0; j < 4; j++)
            res[j] = ROUTED ? acc[i][j] : (acc[i][j] + bias[n + j]);
        float* orow = outp + (size_t)(rowbase + r) * DIMD + n;
        *(float4*)orow = make_float4(res[0], res[1], res[2], res[3]);
    }
}

// ---------------- combine: out += routed contributions + cw@b2 ----------------
__global__ void combine_kernel(const float* __restrict__ b2, float* __restrict__ out)
{
    int t = blockIdx.x;
    int d = threadIdx.x * 4;
    int e0 = g_se[t * 2 + 0], e1 = g_se[t * 2 + 1];
    int r0 = g_off[e0] + g_sp[t * 2 + 0];
    int r1 = g_off[e1] + g_sp[t * 2 + 1];
    float w0 = g_sw[t * 2 + 0], w1 = g_sw[t * 2 + 1];

    float4 y0  = *(const float4*)&g_y[(size_t)r0 * DIMD + d];
    float4 y1  = *(const float4*)&g_y[(size_t)r1 * DIMD + d];
    float4 bb0 = *(const float4*)&b2[(size_t)e0 * DIMD + d];
    float4 bb1 = *(const float4*)&b2[(size_t)e1 * DIMD + d];

    float4* o = (float4*)&out[(size_t)t * DIMD + d];
    float4 c = *o;
    c.x += y0.x + y1.x + w0 * bb0.x + w1 * bb1.x;
    c.y += y0.y + y1.y + w0 * bb0.y + w1 * bb1.y;
    c.z += y0.z + y1.z + w0 * bb0.z + w1 * bb1.z;
    c.w += y0.w + y1.w + w0 * bb0.w + w1 * bb1.w;
    *o = c;
}

// ---------------- launch ----------------
extern "C" void kernel_launch(void* const* d_in, const int* in_sizes, int n_in,
                              void* d_out, int out_size)
{
    const float* x   = (const float*)d_in[0];
    const float* gw  = (const float*)d_in[1];
    const float* gb  = (const float*)d_in[2];
    const float* w1  = (const float*)d_in[3];
    const float* b1  = (const float*)d_in[4];
    const float* w3  = (const float*)d_in[5];
    const float* b3  = (const float*)d_in[6];
    const float* w2  = (const float*)d_in[7];
    const float* b2  = (const float*)d_in[8];
    const float* sw1 = (const float*)d_in[9];
    const float* sb1 = (const float*)d_in[10];
    const float* sw3 = (const float*)d_in[11];
    const float* sb3 = (const float*)d_in[12];
    const float* sw2 = (const float*)d_in[13];
    const float* sb2 = (const float*)d_in[14];
    float* out = (float*)d_out;

    reset_kernel<<<1, 32>>>();
    gate_kernel<<<T_TOKENS / 4, dim3(32, 4)>>>(x, gw, gb);
    scan_kernel<<<1, 1>>>();

    // shared expert path
    up_kernel<SINTER, false><<<dim3(SINTER / 64, T_TOKENS / 128), 256>>>(x, sw1, sb1, sw3, sb3);
    down_kernel<SINTER, false><<<dim3(DIMD / 64, T_TOKENS / 128), 256>>>(sw2, sb2, out);

    // routed expert path (early-exit grid over max tiles)
    up_kernel<INTER, true><<<dim3(INTER / 64, T_TOKENS / 128, NEXP), 256>>>(x, w1, b1, w3, b3);
    down_kernel<INTER, true><<<dim3(DIMD / 64, T_TOKENS / 128, NEXP), 256>>>(w2, nullptr, nullptr);

    combine_kernel<<<T_TOKENS, 256>>>(b2, out);
}

// round 4
// speedup vs baseline: 1.9497x; 1.9497x over previous
#include <cuda_runtime.h>
#include <cuda_bf16.h>
#include <math.h>
#include <stdint.h>

#define T_TOKENS 4096
#define DIMD     1024
#define INTER    1408
#define SINTER   2816
#define NEXP     16

__device__ int   g_cnt[NEXP];
__device__ int   g_off[NEXP];
__device__ int   g_tok[NEXP * T_TOKENS];
__device__ float g_wt [NEXP * T_TOKENS];
__device__ int   g_se [T_TOKENS * 2];
__device__ int   g_sp [T_TOKENS * 2];
__device__ float g_sw [T_TOKENS * 2];
__device__ float g_act[T_TOKENS * 2 * INTER];
__device__ float g_y  [T_TOKENS * 2 * DIMD];
__device__ float g_z  [T_TOKENS * SINTER];

__device__ __forceinline__ uint32_t smem_u32(const void* p) {
    uint32_t a;
    asm("{ .reg .u64 t; cvta.to.shared.u64 t, %1; cvt.u32.u64 %0, t; }" : "=r"(a) : "l"(p));
    return a;
}

#define LDSM_X4(R, a) \
    asm volatile("ldmatrix.sync.aligned.m8n8.x4.shared.b16 {%0,%1,%2,%3}, [%4];" \
        : "=r"((R)[0]), "=r"((R)[1]), "=r"((R)[2]), "=r"((R)[3]) : "r"(a))
#define LDSM_X4T(R, a) \
    asm volatile("ldmatrix.sync.aligned.m8n8.x4.trans.shared.b16 {%0,%1,%2,%3}, [%4];" \
        : "=r"((R)[0]), "=r"((R)[1]), "=r"((R)[2]), "=r"((R)[3]) : "r"(a))
#define MMA_BF16(C, A, b0, b1) \
    asm volatile("mma.sync.aligned.m16n8k16.row.col.f32.bf16.bf16.f32 " \
        "{%0,%1,%2,%3},{%4,%5,%6,%7},{%8,%9},{%0,%1,%2,%3};" \
        : "+f"((C)[0]), "+f"((C)[1]), "+f"((C)[2]), "+f"((C)[3]) \
        : "r"((A)[0]), "r"((A)[1]), "r"((A)[2]), "r"((A)[3]), "r"(b0), "r"(b1))

__device__ __forceinline__ void split_store(float4 v, char* hp, char* lp) {
    __nv_bfloat16 h0 = __float2bfloat16(v.x), h1 = __float2bfloat16(v.y);
    __nv_bfloat16 h2 = __float2bfloat16(v.z), h3 = __float2bfloat16(v.w);
    __nv_bfloat16 l0 = __float2bfloat16(v.x - __bfloat162float(h0));
    __nv_bfloat16 l1 = __float2bfloat16(v.y - __bfloat162float(h1));
    __nv_bfloat16 l2 = __float2bfloat16(v.z - __bfloat162float(h2));
    __nv_bfloat16 l3 = __float2bfloat16(v.w - __bfloat162float(h3));
    __nv_bfloat162 hA = __halves2bfloat162(h0, h1), hB = __halves2bfloat162(h2, h3);
    __nv_bfloat162 lA = __halves2bfloat162(l0, l1), lB = __halves2bfloat162(l2, l3);
    uint2 H, L;
    H.x = *(uint32_t*)&hA; H.y = *(uint32_t*)&hB;
    L.x = *(uint32_t*)&lA; L.y = *(uint32_t*)&lB;
    *(uint2*)hp = H; *(uint2*)lp = L;
}

// ---------- gate / scan ----------
__global__ void reset_kernel() { if (threadIdx.x < NEXP) g_cnt[threadIdx.x] = 0; }

__global__ void gate_kernel(const float* __restrict__ x, const float* __restrict__ gw,
                            const float* __restrict__ gb)
{
    int t = blockIdx.x * blockDim.y + threadIdx.y;
    if (t >= T_TOKENS) return;
    int lane = threadIdx.x;
    float acc[NEXP];
#pragma unroll
    for (int e = 0; e < NEXP; e++) acc[e] = 0.f;
    const float* xr = x + (size_t)t * DIMD;
    for (int d = lane; d < DIMD; d += 32) {
        float xv = xr[d];
        const float* g = gw + (size_t)d * NEXP;
#pragma unroll
        for (int e = 0; e < NEXP; e++) acc[e] += xv * g[e];
    }
#pragma unroll
    for (int e = 0; e < NEXP; e++)
#pragma unroll
        for (int o = 16; o > 0; o >>= 1) acc[e] += __shfl_xor_sync(0xffffffffu, acc[e], o);
    if (lane == 0) {
        float mx = -1e30f;
#pragma unroll
        for (int e = 0; e < NEXP; e++) { acc[e] += gb[e]; mx = fmaxf(mx, acc[e]); }
        float s = 0.f;
#pragma unroll
        for (int e = 0; e < NEXP; e++) { acc[e] = expf(acc[e] - mx); s += acc[e]; }
        int b0 = 0; float v0 = -1.f;
#pragma unroll
        for (int e = 0; e < NEXP; e++) if (acc[e] > v0) { v0 = acc[e]; b0 = e; }
        int b1i = -1; float v1 = -1.f;
#pragma unroll
        for (int e = 0; e < NEXP; e++) if (e != b0 && acc[e] > v1) { v1 = acc[e]; b1i = e; }
        float w0 = v0 / s, w1 = v1 / s;
        int p0 = atomicAdd(&g_cnt[b0], 1);
        g_tok[b0 * T_TOKENS + p0] = t;  g_wt[b0 * T_TOKENS + p0] = w0;
        int p1 = atomicAdd(&g_cnt[b1i], 1);
        g_tok[b1i * T_TOKENS + p1] = t; g_wt[b1i * T_TOKENS + p1] = w1;
        g_se[t*2+0] = b0;  g_sp[t*2+0] = p0;  g_sw[t*2+0] = w0;
        g_se[t*2+1] = b1i; g_sp[t*2+1] = p1;  g_sw[t*2+1] = w1;
    }
}

__global__ void scan_kernel() {
    int s = 0;
    for (int e = 0; e < NEXP; e++) { g_off[e] = s; s += g_cnt[e]; }
}

// ---------- HMMA bf16x3 GEMM: CTA 128x64, BK=32, 8 warps (warp tile 64x16) ----------
// Stage layout: AH 0 (128x80B) | AL 10240 | B1H 20480 (32x144B) | B1L 25088 | B2H 29696 | B2L 34304
template<bool DUAL, bool ROUTED, bool GATHER, int ASEL, int OSEL>
__global__ void __launch_bounds__(256, 1)
hmma_gemm(const float* __restrict__ Aarg,
          const float* __restrict__ B1, const float* __restrict__ B2,
          const float* __restrict__ bias1, const float* __restrict__ bias2,
          float* __restrict__ Oarg, int NN, int KK)
{
    extern __shared__ char smem[];
    const int n0 = blockIdx.x * 64;
    const int m0 = blockIdx.y * 128;
    int M = T_TOKENS, rowbase = 0;
    const int* rowidx = nullptr; const float* wv = nullptr;
    if (ROUTED) {
        int e = blockIdx.z;
        M = g_cnt[e];
        if (m0 >= M) return;
        rowbase = g_off[e];
        B1 += (size_t)e * KK * NN;
        if (DUAL) { B2 += (size_t)e * KK * NN; bias1 += (size_t)e * NN; bias2 += (size_t)e * NN; }
        if (GATHER) { rowidx = g_tok + e * T_TOKENS; wv = g_wt + e * T_TOKENS; }
    }
    const float* A = (ASEL == 0) ? Aarg : (ASEL == 1 ? g_act : g_z);
    float* outp = (OSEL == 0) ? Oarg : (OSEL == 1 ? g_act : (OSEL == 2 ? g_y : g_z));

    const int tid = threadIdx.x, lane = tid & 31, wid = tid >> 5;
    const int wm = wid >> 2, wn = wid & 3;
    const uint32_t sbase = smem_u32(smem);
    const int SSZ = DUAL ? 38912 : 29696;

    float4 pa[4], pb1[2], pb2[2];

    auto prefetch = [&](int k0) {
#pragma unroll
        for (int it = 0; it < 4; it++) {
            int gid = tid + it * 256, row = gid >> 3, f4 = gid & 7;
            int r = m0 + row;
            float4 v = make_float4(0.f, 0.f, 0.f, 0.f);
            if (r < M) {
                const float* ar = GATHER ? A + (size_t)rowidx[r] * KK
                                         : A + (size_t)(rowbase + r) * KK;
                v = *(const float4*)(ar + k0 + f4 * 4);
            }
            pa[it] = v;
        }
#pragma unroll
        for (int it = 0; it < 2; it++) {
            int gid = tid + it * 256, kl = gid >> 4, f4 = gid & 15;
            size_t go = (size_t)(k0 + kl) * NN + n0 + f4 * 4;
            pb1[it] = *(const float4*)(B1 + go);
            if (DUAL) pb2[it] = *(const float4*)(B2 + go);
        }
    };
    auto sts = [&](int st) {
        char* sp = smem + st * SSZ;
#pragma unroll
        for (int it = 0; it < 4; it++) {
            int gid = tid + it * 256, row = gid >> 3, f4 = gid & 7;
            uint32_t o = row * 80 + f4 * 8;
            split_store(pa[it], sp + o, sp + 10240 + o);
        }
#pragma unroll
        for (int it = 0; it < 2; it++) {
            int gid = tid + it * 256, kl = gid >> 4, f4 = gid & 15;
            uint32_t o = kl * 144 + f4 * 8;
            split_store(pb1[it], sp + 20480 + o, sp + 25088 + o);
            if (DUAL) split_store(pb2[it], sp + 29696 + o, sp + 34304 + o);
        }
    };

    float accH[4][2][4], accG[4][2][4];
#pragma unroll
    for (int a = 0; a < 4; a++)
#pragma unroll
        for (int b = 0; b < 2; b++)
#pragma unroll
            for (int c = 0; c < 4; c++) { accH[a][b][c] = 0.f; accG[a][b][c] = 0.f; }

    const int NC = KK / 32;
    prefetch(0);
#pragma unroll 1
    for (int i = 0; i < NC; i++) {
        sts(i & 1);
        __syncthreads();
        if (i + 1 < NC) prefetch((i + 1) * 32);
        uint32_t sb = sbase + (i & 1) * SSZ;
#pragma unroll
        for (int s = 0; s < 2; s++) {
            uint32_t ah[4][4], al[4][4];
#pragma unroll
            for (int mt = 0; mt < 4; mt++) {
                uint32_t ro = (uint32_t)(wm * 64 + mt * 16 + (lane & 15)) * 80
                            + (lane >> 4) * 16 + s * 32;
                LDSM_X4(ah[mt], sb + ro);
                LDSM_X4(al[mt], sb + 10240 + ro);
            }
            uint32_t bo = (uint32_t)(s * 16 + (lane & 15)) * 144
                        + wn * 32 + (lane >> 4) * 16;
            uint32_t b1h[4], b1l[4], b2h[4], b2l[4];
            LDSM_X4T(b1h, sb + 20480 + bo);
            LDSM_X4T(b1l, sb + 25088 + bo);
            if (DUAL) { LDSM_X4T(b2h, sb + 29696 + bo); LDSM_X4T(b2l, sb + 34304 + bo); }
#pragma unroll
            for (int mt = 0; mt < 4; mt++)
#pragma unroll
                for (int nt = 0; nt < 2; nt++) {
                    MMA_BF16(accH[mt][nt], ah[mt], b1h[nt*2], b1h[nt*2+1]);
                    MMA_BF16(accH[mt][nt], ah[mt], b1l[nt*2], b1l[nt*2+1]);
                    MMA_BF16(accH[mt][nt], al[mt], b1h[nt*2], b1h[nt*2+1]);
                    if (DUAL) {
                        MMA_BF16(accG[mt][nt], ah[mt], b2h[nt*2], b2h[nt*2+1]);
                        MMA_BF16(accG[mt][nt], ah[mt], b2l[nt*2], b2l[nt*2+1]);
                        MMA_BF16(accG[mt][nt], al[mt], b2h[nt*2], b2h[nt*2+1]);
                    }
                }
        }
    }

    // ---------- epilogue ----------
#pragma unroll
    for (int mt = 0; mt < 4; mt++) {
        int rb = m0 + wm * 64 + mt * 16 + (lane >> 2);
#pragma unroll
        for (int h = 0; h < 2; h++) {
            int r = rb + h * 8;
            if (r >= M) continue;
            float wgt = GATHER ? wv[r] : 1.f;
            float* orow = outp + (size_t)(rowbase + r) * NN + n0;
#pragma unroll
            for (int nt = 0; nt < 2; nt++) {
                int c = wn * 16 + nt * 8 + (lane & 3) * 2;
                float v0 = accH[mt][nt][h * 2 + 0];
                float v1 = accH[mt][nt][h * 2 + 1];
                if (DUAL) {
                    float h0 = v0 + bias1[n0 + c], h1 = v1 + bias1[n0 + c + 1];
                    float g0 = accG[mt][nt][h * 2 + 0] + bias2[n0 + c];
                    float g1 = accG[mt][nt][h * 2 + 1] + bias2[n0 + c + 1];
                    v0 = (h0 / (1.f + __expf(-h0))) * g0 * wgt;
                    v1 = (h1 / (1.f + __expf(-h1))) * g1 * wgt;
                } else if (!ROUTED) {
                    v0 += bias1[n0 + c];
                    v1 += bias1[n0 + c + 1];
                }
                *(float2*)(orow + c) = make_float2(v0, v1);
            }
        }
    }
}

// ---------- combine ----------
__global__ void combine_kernel(const float* __restrict__ b2, float* __restrict__ out)
{
    int t = blockIdx.x;
    int d = threadIdx.x * 4;
    int e0 = g_se[t*2+0], e1 = g_se[t*2+1];
    int r0 = g_off[e0] + g_sp[t*2+0];
    int r1 = g_off[e1] + g_sp[t*2+1];
    float w0 = g_sw[t*2+0], w1 = g_sw[t*2+1];
    float4 y0 = *(const float4*)&g_y[(size_t)r0 * DIMD + d];
    float4 y1 = *(const float4*)&g_y[(size_t)r1 * DIMD + d];
    float4 a0 = *(const float4*)&b2[(size_t)e0 * DIMD + d];
    float4 a1 = *(const float4*)&b2[(size_t)e1 * DIMD + d];
    float4* o = (float4*)&out[(size_t)t * DIMD + d];
    float4 c = *o;
    c.x += y0.x + y1.x + w0 * a0.x + w1 * a1.x;
    c.y += y0.y + y1.y + w0 * a0.y + w1 * a1.y;
    c.z += y0.z + y1.z + w0 * a0.z + w1 * a1.z;
    c.w += y0.w + y1.w + w0 * a0.w + w1 * a1.w;
    *o = c;
}

// ---------- launch ----------
extern "C" void kernel_launch(void* const* d_in, const int* in_sizes, int n_in,
                              void* d_out, int out_size)
{
    const float* x   = (const float*)d_in[0];
    const float* gw  = (const float*)d_in[1];
    const float* gb  = (const float*)d_in[2];
    const float* w1  = (const float*)d_in[3];
    const float* b1  = (const float*)d_in[4];
    const float* w3  = (const float*)d_in[5];
    const float* b3  = (const float*)d_in[6];
    const float* w2  = (const float*)d_in[7];
    const float* b2  = (const float*)d_in[8];
    const float* sw1 = (const float*)d_in[9];
    const float* sb1 = (const float*)d_in[10];
    const float* sw3 = (const float*)d_in[11];
    const float* sb3 = (const float*)d_in[12];
    const float* sw2 = (const float*)d_in[13];
    const float* sb2 = (const float*)d_in[14];
    float* out = (float*)d_out;

    const int SM_D = 2 * 38912;   // 77824
    const int SM_S = 2 * 29696;   // 59392
    cudaFuncSetAttribute(hmma_gemm<true,  false, false, 0, 3>, cudaFuncAttributeMaxDynamicSharedMemorySize, SM_D);
    cudaFuncSetAttribute(hmma_gemm<true,  true,  true,  0, 1>, cudaFuncAttributeMaxDynamicSharedMemorySize, SM_D);
    cudaFuncSetAttribute(hmma_gemm<false, false, false, 2, 0>, cudaFuncAttributeMaxDynamicSharedMemorySize, SM_S);
    cudaFuncSetAttribute(hmma_gemm<false, true,  false, 1, 2>, cudaFuncAttributeMaxDynamicSharedMemorySize, SM_S);

    reset_kernel<<<1, 32>>>();
    gate_kernel<<<T_TOKENS / 4, dim3(32, 4)>>>(x, gw, gb);
    scan_kernel<<<1, 1>>>();

    // shared expert: up (dual SwiGLU -> g_z), down (g_z @ sw2 + sb2 -> out)
    hmma_gemm<true,  false, false, 0, 3><<<dim3(SINTER/64, T_TOKENS/128), 256, SM_D>>>(
        x, sw1, sw3, sb1, sb3, nullptr, SINTER, DIMD);
    hmma_gemm<false, false, false, 2, 0><<<dim3(DIMD/64, T_TOKENS/128), 256, SM_S>>>(
        nullptr, sw2, nullptr, sb2, nullptr, out, DIMD, SINTER);

    // routed experts: up (gather + dual SwiGLU -> g_act), down (g_act @ w2 -> g_y)
    hmma_gemm<true,  true,  true,  0, 1><<<dim3(INTER/64, T_TOKENS/128, NEXP), 256, SM_D>>>(
        x, w1, w3, b1, b3, nullptr, INTER, DIMD);
    hmma_gemm<false, true,  false, 1, 2><<<dim3(DIMD/64, T_TOKENS/128, NEXP), 256, SM_S>>>(
        nullptr, w2, nullptr, nullptr, nullptr, nullptr, DIMD, INTER);

    combine_kernel<<<T_TOKENS, 256>>>(b2, out);
}

// round 6
// speedup vs baseline: 2.2648x; 1.1616x over previous
#include <cuda_runtime.h>
#include <cuda_bf16.h>
#include <math.h>
#include <stdint.h>

#define T_TOKENS 4096
#define DIMD     1024
#define INTER    1408
#define SINTER   2816
#define NEXP     16

__device__ int   g_cnt[NEXP];
__device__ int   g_off[NEXP];
__device__ int   g_tok[NEXP * T_TOKENS];
__device__ float g_wt [NEXP * T_TOKENS];
__device__ int   g_se [T_TOKENS * 2];
__device__ int   g_sp [T_TOKENS * 2];
__device__ float g_sw [T_TOKENS * 2];
__device__ float g_act[T_TOKENS * 2 * INTER];
__device__ float g_y  [T_TOKENS * 2 * DIMD];
__device__ float g_z  [T_TOKENS * SINTER];

__device__ __forceinline__ uint32_t smem_u32(const void* p) {
    uint32_t a;
    asm("{ .reg .u64 t; cvta.to.shared.u64 t, %1; cvt.u32.u64 %0, t; }" : "=r"(a) : "l"(p));
    return a;
}

#define LDSM_X4(R, a) \
    asm volatile("ldmatrix.sync.aligned.m8n8.x4.shared.b16 {%0,%1,%2,%3}, [%4];" \
        : "=r"((R)[0]), "=r"((R)[1]), "=r"((R)[2]), "=r"((R)[3]) : "r"(a))
#define LDSM_X4T(R, a) \
    asm volatile("ldmatrix.sync.aligned.m8n8.x4.trans.shared.b16 {%0,%1,%2,%3}, [%4];" \
        : "=r"((R)[0]), "=r"((R)[1]), "=r"((R)[2]), "=r"((R)[3]) : "r"(a))
#define MMA_BF16(C, A, b0, b1) \
    asm volatile("mma.sync.aligned.m16n8k16.row.col.f32.bf16.bf16.f32 " \
        "{%0,%1,%2,%3},{%4,%5,%6,%7},{%8,%9},{%0,%1,%2,%3};" \
        : "+f"((C)[0]), "+f"((C)[1]), "+f"((C)[2]), "+f"((C)[3]) \
        : "r"((A)[0]), "r"((A)[1]), "r"((A)[2]), "r"((A)[3]), "r"(b0), "r"(b1))

__device__ __forceinline__ void split_store(float4 v, char* hp, char* lp) {
    __nv_bfloat16 h0 = __float2bfloat16(v.x), h1 = __float2bfloat16(v.y);
    __nv_bfloat16 h2 = __float2bfloat16(v.z), h3 = __float2bfloat16(v.w);
    __nv_bfloat16 l0 = __float2bfloat16(v.x - __bfloat162float(h0));
    __nv_bfloat16 l1 = __float2bfloat16(v.y - __bfloat162float(h1));
    __nv_bfloat16 l2 = __float2bfloat16(v.z - __bfloat162float(h2));
    __nv_bfloat16 l3 = __float2bfloat16(v.w - __bfloat162float(h3));
    __nv_bfloat162 hA = __halves2bfloat162(h0, h1), hB = __halves2bfloat162(h2, h3);
    __nv_bfloat162 lA = __halves2bfloat162(l0, l1), lB = __halves2bfloat162(l2, l3);
    uint2 H, L;
    H.x = *(uint32_t*)&hA; H.y = *(uint32_t*)&hB;
    L.x = *(uint32_t*)&lA; L.y = *(uint32_t*)&lB;
    *(uint2*)hp = H; *(uint2*)lp = L;
}

// ---------- gate / scan ----------
__global__ void reset_kernel() { if (threadIdx.x < NEXP) g_cnt[threadIdx.x] = 0; }

__global__ void gate_kernel(const float* __restrict__ x, const float* __restrict__ gw,
                            const float* __restrict__ gb)
{
    int t = blockIdx.x * blockDim.y + threadIdx.y;
    if (t >= T_TOKENS) return;
    int lane = threadIdx.x;
    float acc[NEXP];
#pragma unroll
    for (int e = 0; e < NEXP; e++) acc[e] = 0.f;
    const float* xr = x + (size_t)t * DIMD;
    for (int d = lane; d < DIMD; d += 32) {
        float xv = xr[d];
        const float* g = gw + (size_t)d * NEXP;
#pragma unroll
        for (int e = 0; e < NEXP; e++) acc[e] += xv * g[e];
    }
#pragma unroll
    for (int e = 0; e < NEXP; e++)
#pragma unroll
        for (int o = 16; o > 0; o >>= 1) acc[e] += __shfl_xor_sync(0xffffffffu, acc[e], o);
    if (lane == 0) {
        float mx = -1e30f;
#pragma unroll
        for (int e = 0; e < NEXP; e++) { acc[e] += gb[e]; mx = fmaxf(mx, acc[e]); }
        float s = 0.f;
#pragma unroll
        for (int e = 0; e < NEXP; e++) { acc[e] = expf(acc[e] - mx); s += acc[e]; }
        int b0 = 0; float v0 = -1.f;
#pragma unroll
        for (int e = 0; e < NEXP; e++) if (acc[e] > v0) { v0 = acc[e]; b0 = e; }
        int b1i = -1; float v1 = -1.f;
#pragma unroll
        for (int e = 0; e < NEXP; e++) if (e != b0 && acc[e] > v1) { v1 = acc[e]; b1i = e; }
        float w0 = v0 / s, w1 = v1 / s;
        int p0 = atomicAdd(&g_cnt[b0], 1);
        g_tok[b0 * T_TOKENS + p0] = t;  g_wt[b0 * T_TOKENS + p0] = w0;
        int p1 = atomicAdd(&g_cnt[b1i], 1);
        g_tok[b1i * T_TOKENS + p1] = t; g_wt[b1i * T_TOKENS + p1] = w1;
        g_se[t*2+0] = b0;  g_sp[t*2+0] = p0;  g_sw[t*2+0] = w0;
        g_se[t*2+1] = b1i; g_sp[t*2+1] = p1;  g_sw[t*2+1] = w1;
    }
}

__global__ void scan_kernel() {
    int s = 0;
    for (int e = 0; e < NEXP; e++) { g_off[e] = s; s += g_cnt[e]; }
}

// ---------- HMMA bf16x3 GEMM: CTA 128x64, BK=32, 8 warps, target 2 CTAs/SM ----------
// Stage layout: AH 0 (128x80B) | AL 10240 | B1H 20480 (32x144B) | B1L 25088 | B2H 29696 | B2L 34304
template<bool DUAL, bool ROUTED, bool GATHER, int ASEL, int OSEL>
__global__ void __launch_bounds__(256, 2)
hmma_gemm(const float* __restrict__ Aarg,
          const float* __restrict__ B1, const float* __restrict__ B2,
          const float* __restrict__ bias1, const float* __restrict__ bias2,
          float* __restrict__ Oarg, int NN, int KK)
{
    extern __shared__ char smem[];
    const int n0 = blockIdx.x * 64;
    const int m0 = blockIdx.y * 128;
    int M = T_TOKENS, rowbase = 0;
    const int* rowidx = nullptr; const float* wv = nullptr;
    if (ROUTED) {
        int e = blockIdx.z;
        M = g_cnt[e];
        if (m0 >= M) return;
        rowbase = g_off[e];
        B1 += (size_t)e * KK * NN;
        if (DUAL) { B2 += (size_t)e * KK * NN; bias1 += (size_t)e * NN; bias2 += (size_t)e * NN; }
        if (GATHER) { rowidx = g_tok + e * T_TOKENS; wv = g_wt + e * T_TOKENS; }
    }
    const float* A = (ASEL == 0) ? Aarg : (ASEL == 1 ? g_act : g_z);
    float* outp = (OSEL == 0) ? Oarg : (OSEL == 1 ? g_act : (OSEL == 2 ? g_y : g_z));

    const int tid = threadIdx.x, lane = tid & 31, wid = tid >> 5;
    const int wm = wid >> 2, wn = wid & 3;
    const uint32_t sbase = smem_u32(smem);
    const int SSZ = DUAL ? 38912 : 29696;

    // direct load -> split -> store (no prefetch registers; 2 CTAs/SM hide LDG)
    auto stage = [&](int k0, int st) {
        char* sp = smem + st * SSZ;
#pragma unroll
        for (int it = 0; it < 4; it++) {               // A: 128 rows x 8 float4
            int gid = tid + it * 256, row = gid >> 3, f4 = gid & 7;
            int r = m0 + row;
            float4 v = make_float4(0.f, 0.f, 0.f, 0.f);
            if (r < M) {
                const float* ar = GATHER ? A + (size_t)rowidx[r] * KK
                                         : A + (size_t)(rowbase + r) * KK;
                v = *(const float4*)(ar + k0 + f4 * 4);
            }
            uint32_t o = row * 80 + f4 * 8;
            split_store(v, sp + o, sp + 10240 + o);
        }
#pragma unroll
        for (int it = 0; it < 2; it++) {               // B: 32 k-rows x 16 float4
            int gid = tid + it * 256, kl = gid >> 4, f4 = gid & 15;
            size_t go = (size_t)(k0 + kl) * NN + n0 + f4 * 4;
            uint32_t o = kl * 144 + f4 * 8;
            split_store(*(const float4*)(B1 + go), sp + 20480 + o, sp + 25088 + o);
            if (DUAL) split_store(*(const float4*)(B2 + go), sp + 29696 + o, sp + 34304 + o);
        }
    };

    float accH[4][2][4], accG[4][2][4];
#pragma unroll
    for (int a = 0; a < 4; a++)
#pragma unroll
        for (int b = 0; b < 2; b++)
#pragma unroll
            for (int c = 0; c < 4; c++) { accH[a][b][c] = 0.f; accG[a][b][c] = 0.f; }

    const int NC = KK / 32;
    stage(0, 0);
#pragma unroll 1
    for (int i = 0; i < NC; i++) {
        __syncthreads();
        // stage next chunk into other buffer; cross-iteration hazards separated by
        // the next iteration's barrier (write (i+1)&1 vs read i&1 here).
        if (i + 1 < NC) stage((i + 1) * 32, (i + 1) & 1);
        uint32_t sb = sbase + (i & 1) * SSZ;
#pragma unroll
        for (int s = 0; s < 2; s++) {
            uint32_t bo = (uint32_t)(s * 16 + (lane & 15)) * 144
                        + wn * 32 + (lane >> 4) * 16;
            uint32_t b1h[4], b1l[4], b2h[4], b2l[4];
            LDSM_X4T(b1h, sb + 20480 + bo);
            LDSM_X4T(b1l, sb + 25088 + bo);
            if (DUAL) { LDSM_X4T(b2h, sb + 29696 + bo); LDSM_X4T(b2l, sb + 34304 + bo); }
#pragma unroll
            for (int mt = 0; mt < 4; mt++) {
                uint32_t ah[4], al[4];
                uint32_t ro = (uint32_t)(wm * 64 + mt * 16 + (lane & 15)) * 80
                            + (lane >> 4) * 16 + s * 32;
                LDSM_X4(ah, sb + ro);
                LDSM_X4(al, sb + 10240 + ro);
#pragma unroll
                for (int nt = 0; nt < 2; nt++) {
                    MMA_BF16(accH[mt][nt], ah, b1h[nt*2], b1h[nt*2+1]);
                    MMA_BF16(accH[mt][nt], ah, b1l[nt*2], b1l[nt*2+1]);
                    MMA_BF16(accH[mt][nt], al, b1h[nt*2], b1h[nt*2+1]);
                    if (DUAL) {
                        MMA_BF16(accG[mt][nt], ah, b2h[nt*2], b2h[nt*2+1]);
                        MMA_BF16(accG[mt][nt], ah, b2l[nt*2], b2l[nt*2+1]);
                        MMA_BF16(accG[mt][nt], al, b2h[nt*2], b2h[nt*2+1]);
                    }
                }
            }
        }
    }

    // ---------- epilogue ----------
#pragma unroll
    for (int mt = 0; mt < 4; mt++) {
        int rb = m0 + wm * 64 + mt * 16 + (lane >> 2);
#pragma unroll
        for (int h = 0; h < 2; h++) {
            int r = rb + h * 8;
            if (r >= M) continue;
            float wgt = GATHER ? wv[r] : 1.f;
            float* orow = outp + (size_t)(rowbase + r) * NN + n0;
#pragma unroll
            for (int nt = 0; nt < 2; nt++) {
                int c = wn * 16 + nt * 8 + (lane & 3) * 2;
                float v0 = accH[mt][nt][h * 2 + 0];
                float v1 = accH[mt][nt][h * 2 + 1];
                if (DUAL) {
                    float h0 = v0 + bias1[n0 + c], h1 = v1 + bias1[n0 + c + 1];
                    float g0 = accG[mt][nt][h * 2 + 0] + bias2[n0 + c];
                    float g1 = accG[mt][nt][h * 2 + 1] + bias2[n0 + c + 1];
                    v0 = (h0 / (1.f + __expf(-h0))) * g0 * wgt;
                    v1 = (h1 / (1.f + __expf(-h1))) * g1 * wgt;
                } else if (!ROUTED) {
                    v0 += bias1[n0 + c];
                    v1 += bias1[n0 + c + 1];
                }
                *(float2*)(orow + c) = make_float2(v0, v1);
            }
        }
    }
}

// ---------- combine ----------
__global__ void combine_kernel(const float* __restrict__ b2, float* __restrict__ out)
{
    int t = blockIdx.x;
    int d = threadIdx.x * 4;
    int e0 = g_se[t*2+0], e1 = g_se[t*2+1];
    int r0 = g_off[e0] + g_sp[t*2+0];
    int r1 = g_off[e1] + g_sp[t*2+1];
    float w0 = g_sw[t*2+0], w1 = g_sw[t*2+1];
    float4 y0 = *(const float4*)&g_y[(size_t)r0 * DIMD + d];
    float4 y1 = *(const float4*)&g_y[(size_t)r1 * DIMD + d];
    float4 a0 = *(const float4*)&b2[(size_t)e0 * DIMD + d];
    float4 a1 = *(const float4*)&b2[(size_t)e1 * DIMD + d];
    float4* o = (float4*)&out[(size_t)t * DIMD + d];
    float4 c = *o;
    c.x += y0.x + y1.x + w0 * a0.x + w1 * a1.x;
    c.y += y0.y + y1.y + w0 * a0.y + w1 * a1.y;
    c.z += y0.z + y1.z + w0 * a0.z + w1 * a1.z;
    c.w += y0.w + y1.w + w0 * a0.w + w1 * a1.w;
    *o = c;
}

// ---------- launch ----------
extern "C" void kernel_launch(void* const* d_in, const int* in_sizes, int n_in,
                              void* d_out, int out_size)
{
    const float* x   = (const float*)d_in[0];
    const float* gw  = (const float*)d_in[1];
    const float* gb  = (const float*)d_in[2];
    const float* w1  = (const float*)d_in[3];
    const float* b1  = (const float*)d_in[4];
    const float* w3  = (const float*)d_in[5];
    const float* b3  = (const float*)d_in[6];
    const float* w2  = (const float*)d_in[7];
    const float* b2  = (const float*)d_in[8];
    const float* sw1 = (const float*)d_in[9];
    const float* sb1 = (const float*)d_in[10];
    const float* sw3 = (const float*)d_in[11];
    const float* sb3 = (const float*)d_in[12];
    const float* sw2 = (const float*)d_in[13];
    const float* sb2 = (const float*)d_in[14];
    float* out = (float*)d_out;

    const int SM_D = 2 * 38912;   // 77824 (x2 CTAs = 155648 <= 228KB)
    const int SM_S = 2 * 29696;   // 59392
    cudaFuncSetAttribute(hmma_gemm<true,  false, false, 0, 3>, cudaFuncAttributeMaxDynamicSharedMemorySize, SM_D);
    cudaFuncSetAttribute(hmma_gemm<true,  true,  true,  0, 1>, cudaFuncAttributeMaxDynamicSharedMemorySize, SM_D);
    cudaFuncSetAttribute(hmma_gemm<false, false, false, 2, 0>, cudaFuncAttributeMaxDynamicSharedMemorySize, SM_S);
    cudaFuncSetAttribute(hmma_gemm<false, true,  false, 1, 2>, cudaFuncAttributeMaxDynamicSharedMemorySize, SM_S);

    reset_kernel<<<1, 32>>>();
    gate_kernel<<<T_TOKENS / 4, dim3(32, 4)>>>(x, gw, gb);
    scan_kernel<<<1, 1>>>();

    // shared expert
    hmma_gemm<true,  false, false, 0, 3><<<dim3(SINTER/64, T_TOKENS/128), 256, SM_D>>>(
        x, sw1, sw3, sb1, sb3, nullptr, SINTER, DIMD);
    hmma_gemm<false, false, false, 2, 0><<<dim3(DIMD/64, T_TOKENS/128), 256, SM_S>>>(
        nullptr, sw2, nullptr, sb2, nullptr, out, DIMD, SINTER);

    // routed experts
    hmma_gemm<true,  true,  true,  0, 1><<<dim3(INTER/64, T_TOKENS/128, NEXP), 256, SM_D>>>(
        x, w1, w3, b1, b3, nullptr, INTER, DIMD);
    hmma_gemm<false, true,  false, 1, 2><<<dim3(DIMD/64, T_TOKENS/128, NEXP), 256, SM_S>>>(
        nullptr, w2, nullptr, nullptr, nullptr, nullptr, DIMD, INTER);

    combine_kernel<<<T_TOKENS, 256>>>(b2, out);
}

// round 7
// speedup vs baseline: 2.2941x; 1.0129x over previous
#include <cuda_runtime.h>
#include <cuda_bf16.h>
#include <math.h>
#include <stdint.h>

#define T_TOKENS 4096
#define DIMD     1024
#define INTER    1408
#define SINTER   2816
#define NEXP     16
typedef __nv_bfloat16 bf16;

__device__ int   g_cnt[NEXP];
__device__ int   g_off[NEXP];
__device__ int   g_tok[NEXP * T_TOKENS];
__device__ float g_wt [NEXP * T_TOKENS];
__device__ int   g_se [T_TOKENS * 2];
__device__ int   g_sp [T_TOKENS * 2];
__device__ float g_sw [T_TOKENS * 2];
__device__ float g_y  [T_TOKENS * 2 * DIMD];

// persistent bf16 hi/lo splits
__device__ bf16 s_xh [T_TOKENS * DIMD],      s_xl [T_TOKENS * DIMD];
__device__ bf16 s_w1h[NEXP * DIMD * INTER],  s_w1l[NEXP * DIMD * INTER];
__device__ bf16 s_w3h[NEXP * DIMD * INTER],  s_w3l[NEXP * DIMD * INTER];
__device__ bf16 s_w2h[NEXP * INTER * DIMD],  s_w2l[NEXP * INTER * DIMD];
__device__ bf16 s_u1h[DIMD * SINTER],        s_u1l[DIMD * SINTER];
__device__ bf16 s_u3h[DIMD * SINTER],        s_u3l[DIMD * SINTER];
__device__ bf16 s_u2h[SINTER * DIMD],        s_u2l[SINTER * DIMD];
__device__ bf16 s_ah [T_TOKENS * 2 * INTER], s_al [T_TOKENS * 2 * INTER];
__device__ bf16 s_zh [T_TOKENS * SINTER],    s_zl [T_TOKENS * SINTER];

__device__ __forceinline__ uint32_t smem_u32(const void* p) {
    uint32_t a;
    asm("{ .reg .u64 t; cvta.to.shared.u64 t, %1; cvt.u32.u64 %0, t; }" : "=r"(a) : "l"(p));
    return a;
}
#define LDSM_X4(R, a) \
    asm volatile("ldmatrix.sync.aligned.m8n8.x4.shared.b16 {%0,%1,%2,%3}, [%4];" \
        : "=r"((R)[0]), "=r"((R)[1]), "=r"((R)[2]), "=r"((R)[3]) : "r"(a))
#define LDSM_X4T(R, a) \
    asm volatile("ldmatrix.sync.aligned.m8n8.x4.trans.shared.b16 {%0,%1,%2,%3}, [%4];" \
        : "=r"((R)[0]), "=r"((R)[1]), "=r"((R)[2]), "=r"((R)[3]) : "r"(a))
#define MMA_BF16(C, A, b0, b1) \
    asm volatile("mma.sync.aligned.m16n8k16.row.col.f32.bf16.bf16.f32 " \
        "{%0,%1,%2,%3},{%4,%5,%6,%7},{%8,%9},{%0,%1,%2,%3};" \
        : "+f"((C)[0]), "+f"((C)[1]), "+f"((C)[2]), "+f"((C)[3]) \
        : "r"((A)[0]), "r"((A)[1]), "r"((A)[2]), "r"((A)[3]), "r"(b0), "r"(b1))
#define CP16(dst, src) \
    asm volatile("cp.async.cg.shared.global [%0], [%1], 16;" :: "r"(dst), "l"(src))
#define CPC()  asm volatile("cp.async.commit_group;")
#define CPW0() asm volatile("cp.async.wait_group 0;")

__device__ __forceinline__ uint32_t pack_bf2(float a, float b) {
    __nv_bfloat162 t = __halves2bfloat162(__float2bfloat16(a), __float2bfloat16(b));
    return *(uint32_t*)&t;
}

// ---------- split: fp32 -> (hi, lo) bf16, one-time ----------
template<int DST>
__global__ void split_kernel(const float* __restrict__ in, size_t n4)
{
    bf16 *h, *l;
    if (DST == 0) { h = s_xh;  l = s_xl;  }
    else if (DST == 1) { h = s_w1h; l = s_w1l; }
    else if (DST == 2) { h = s_w3h; l = s_w3l; }
    else if (DST == 3) { h = s_w2h; l = s_w2l; }
    else if (DST == 4) { h = s_u1h; l = s_u1l; }
    else if (DST == 5) { h = s_u3h; l = s_u3l; }
    else               { h = s_u2h; l = s_u2l; }
    size_t i = (size_t)blockIdx.x * blockDim.x + threadIdx.x;
    if (i >= n4) return;
    float4 v = *(const float4*)(in + i * 4);
    bf16 h0 = __float2bfloat16(v.x), h1 = __float2bfloat16(v.y);
    bf16 h2 = __float2bfloat16(v.z), h3 = __float2bfloat16(v.w);
    uint2 H, L;
    __nv_bfloat162 a = __halves2bfloat162(h0, h1), b = __halves2bfloat162(h2, h3);
    H.x = *(uint32_t*)&a; H.y = *(uint32_t*)&b;
    __nv_bfloat162 c = __halves2bfloat162(__float2bfloat16(v.x - __bfloat162float(h0)),
                                          __float2bfloat16(v.y - __bfloat162float(h1)));
    __nv_bfloat162 d = __halves2bfloat162(__float2bfloat16(v.z - __bfloat162float(h2)),
                                          __float2bfloat16(v.w - __bfloat162float(h3)));
    L.x = *(uint32_t*)&c; L.y = *(uint32_t*)&d;
    *(uint2*)(h + i * 4) = H;
    *(uint2*)(l + i * 4) = L;
}

// ---------- gate / scan ----------
__global__ void reset_kernel() { if (threadIdx.x < NEXP) g_cnt[threadIdx.x] = 0; }

__global__ void gate_kernel(const float* __restrict__ x, const float* __restrict__ gw,
                            const float* __restrict__ gb)
{
    int t = blockIdx.x * blockDim.y + threadIdx.y;
    if (t >= T_TOKENS) return;
    int lane = threadIdx.x;
    float acc[NEXP];
#pragma unroll
    for (int e = 0; e < NEXP; e++) acc[e] = 0.f;
    const float* xr = x + (size_t)t * DIMD;
    for (int d = lane; d < DIMD; d += 32) {
        float xv = xr[d];
        const float* g = gw + (size_t)d * NEXP;
#pragma unroll
        for (int e = 0; e < NEXP; e++) acc[e] += xv * g[e];
    }
#pragma unroll
    for (int e = 0; e < NEXP; e++)
#pragma unroll
        for (int o = 16; o > 0; o >>= 1) acc[e] += __shfl_xor_sync(0xffffffffu, acc[e], o);
    if (lane == 0) {
        float mx = -1e30f;
#pragma unroll
        for (int e = 0; e < NEXP; e++) { acc[e] += gb[e]; mx = fmaxf(mx, acc[e]); }
        float s = 0.f;
#pragma unroll
        for (int e = 0; e < NEXP; e++) { acc[e] = expf(acc[e] - mx); s += acc[e]; }
        int b0 = 0; float v0 = -1.f;
#pragma unroll
        for (int e = 0; e < NEXP; e++) if (acc[e] > v0) { v0 = acc[e]; b0 = e; }
        int b1i = -1; float v1 = -1.f;
#pragma unroll
        for (int e = 0; e < NEXP; e++) if (e != b0 && acc[e] > v1) { v1 = acc[e]; b1i = e; }
        float w0 = v0 / s, w1 = v1 / s;
        int p0 = atomicAdd(&g_cnt[b0], 1);
        g_tok[b0 * T_TOKENS + p0] = t;  g_wt[b0 * T_TOKENS + p0] = w0;
        int p1 = atomicAdd(&g_cnt[b1i], 1);
        g_tok[b1i * T_TOKENS + p1] = t; g_wt[b1i * T_TOKENS + p1] = w1;
        g_se[t*2+0] = b0;  g_sp[t*2+0] = p0;  g_sw[t*2+0] = w0;
        g_se[t*2+1] = b1i; g_sp[t*2+1] = p1;  g_sw[t*2+1] = w1;
    }
}

__global__ void scan_kernel() {
    int s = 0;
    for (int e = 0; e < NEXP; e++) { g_off[e] = s; s += g_cnt[e]; }
}

// ---------- HMMA bf16x3 GEMM, pure-bf16 inputs via cp.async ----------
// CTA 128x64, BK=32, 8 warps, 2 CTAs/SM.
// Stage: AH 0 (128x80B) | AL 10240 | B1H 20480 (32x144B) | B1L 25088 | B2H 29696 | B2L 34304
template<bool DUAL, bool ROUTED, bool GATHER, int ASEL, int BSEL, int OSEL>
__global__ void __launch_bounds__(256, 2)
hmma_gemm(const float* __restrict__ bias1, const float* __restrict__ bias2,
          float* __restrict__ Oarg, int NN, int KK)
{
    extern __shared__ char smem[];
    const int n0 = blockIdx.x * 64;
    const int m0 = blockIdx.y * 128;
    int M = T_TOKENS, rowbase = 0;
    const int* rowidx = nullptr; const float* wv = nullptr;

    const bf16 *Ah = (ASEL == 0) ? s_xh : (ASEL == 1 ? s_ah : s_zh);
    const bf16 *Al = (ASEL == 0) ? s_xl : (ASEL == 1 ? s_al : s_zl);
    const bf16 *B1h, *B1l, *B2h = nullptr, *B2l = nullptr;
    if (BSEL == 0)      { B1h = s_w1h; B1l = s_w1l; B2h = s_w3h; B2l = s_w3l; }
    else if (BSEL == 1) { B1h = s_w2h; B1l = s_w2l; }
    else if (BSEL == 2) { B1h = s_u1h; B1l = s_u1l; B2h = s_u3h; B2l = s_u3l; }
    else                { B1h = s_u2h; B1l = s_u2l; }

    if (ROUTED) {
        int e = blockIdx.z;
        M = g_cnt[e];
        if (m0 >= M) return;
        rowbase = g_off[e];
        size_t wo = (size_t)e * KK * NN;
        B1h += wo; B1l += wo;
        if (DUAL) { B2h += wo; B2l += wo; bias1 += (size_t)e * NN; bias2 += (size_t)e * NN; }
        if (GATHER) { rowidx = g_tok + e * T_TOKENS; wv = g_wt + e * T_TOKENS; }
    }

    const int tid = threadIdx.x, lane = tid & 31, wid = tid >> 5;
    const int wm = wid >> 2, wn = wid & 3;
    const uint32_t sbase = smem_u32(smem);
    const int SSZ = DUAL ? 38912 : 29696;

    // per-thread A copy tasks (2): row = task>>2 (0..127), c = task&3 (16B chunk)
    const bf16 *apH[2], *apL[2];
    uint32_t adst[2];
#pragma unroll
    for (int it = 0; it < 2; it++) {
        int task = tid + it * 256, row = task >> 2, c = task & 3;
        int r = m0 + row; if (r >= M) r = M - 1;           // clamp; epilogue skips OOB rows
        size_t ro = GATHER ? (size_t)rowidx[r] * KK : (size_t)(rowbase + r) * KK;
        apH[it] = Ah + ro + c * 8;
        apL[it] = Al + ro + c * 8;
        adst[it] = row * 80 + c * 16;
    }
    // B copy task: kl = tid>>3 (0..31), c = tid&7
    const int bkl = tid >> 3, bc = tid & 7;
    const size_t bbase = (size_t)bkl * NN + n0 + bc * 8;
    const uint32_t bdst = bkl * 144 + bc * 16;

    auto stage = [&](int k0, int st) {
        uint32_t sp = sbase + st * SSZ;
#pragma unroll
        for (int it = 0; it < 2; it++) {
            uint32_t d = sp + adst[it];
            CP16(d, apH[it] + k0);
            CP16(d + 10240, apL[it] + k0);
        }
        size_t go = bbase + (size_t)k0 * NN;
        uint32_t d = sp + 20480 + bdst;
        CP16(d, B1h + go);
        CP16(d + 4608, B1l + go);
        if (DUAL) {
            CP16(d + 9216,  B2h + go);
            CP16(d + 13824, B2l + go);
        }
    };

    float accH[4][2][4], accG[4][2][4];
#pragma unroll
    for (int a = 0; a < 4; a++)
#pragma unroll
        for (int b = 0; b < 2; b++)
#pragma unroll
            for (int c = 0; c < 4; c++) { accH[a][b][c] = 0.f; accG[a][b][c] = 0.f; }

    const int NC = KK / 32;
    stage(0, 0); CPC();
#pragma unroll 1
    for (int i = 0; i < NC; i++) {
        CPW0();
        __syncthreads();
        if (i + 1 < NC) { stage((i + 1) * 32, (i + 1) & 1); CPC(); }
        uint32_t sb = sbase + (i & 1) * SSZ;
#pragma unroll
        for (int s = 0; s < 2; s++) {
            uint32_t bo = (uint32_t)(s * 16 + (lane & 15)) * 144
                        + wn * 32 + (lane >> 4) * 16;
            uint32_t b1h[4], b1l[4], b2h[4], b2l[4];
            LDSM_X4T(b1h, sb + 20480 + bo);
            LDSM_X4T(b1l, sb + 25088 + bo);
            if (DUAL) { LDSM_X4T(b2h, sb + 29696 + bo); LDSM_X4T(b2l, sb + 34304 + bo); }
#pragma unroll
            for (int mt = 0; mt < 4; mt++) {
                uint32_t ah[4], al[4];
                uint32_t ro = (uint32_t)(wm * 64 + mt * 16 + (lane & 15)) * 80
                            + (lane >> 4) * 16 + s * 32;
                LDSM_X4(ah, sb + ro);
                LDSM_X4(al, sb + 10240 + ro);
#pragma unroll
                for (int nt = 0; nt < 2; nt++) {
                    MMA_BF16(accH[mt][nt], ah, b1h[nt*2], b1h[nt*2+1]);
                    MMA_BF16(accH[mt][nt], ah, b1l[nt*2], b1l[nt*2+1]);
                    MMA_BF16(accH[mt][nt], al, b1h[nt*2], b1h[nt*2+1]);
                    if (DUAL) {
                        MMA_BF16(accG[mt][nt], ah, b2h[nt*2], b2h[nt*2+1]);
                        MMA_BF16(accG[mt][nt], ah, b2l[nt*2], b2l[nt*2+1]);
                        MMA_BF16(accG[mt][nt], al, b2h[nt*2], b2h[nt*2+1]);
                    }
                }
            }
        }
    }

    // ---------- epilogue ----------
#pragma unroll
    for (int mt = 0; mt < 4; mt++) {
        int rb = m0 + wm * 64 + mt * 16 + (lane >> 2);
#pragma unroll
        for (int h = 0; h < 2; h++) {
            int r = rb + h * 8;
            if (r >= M) continue;
            float wgt = GATHER ? wv[r] : 1.f;
            size_t rowoff = (size_t)(rowbase + r) * NN + n0;
#pragma unroll
            for (int nt = 0; nt < 2; nt++) {
                int c = wn * 16 + nt * 8 + (lane & 3) * 2;
                float v0 = accH[mt][nt][h * 2 + 0];
                float v1 = accH[mt][nt][h * 2 + 1];
                if (DUAL) {
                    float h0 = v0 + bias1[n0 + c], h1 = v1 + bias1[n0 + c + 1];
                    float g0 = accG[mt][nt][h * 2 + 0] + bias2[n0 + c];
                    float g1 = accG[mt][nt][h * 2 + 1] + bias2[n0 + c + 1];
                    v0 = (h0 / (1.f + __expf(-h0))) * g0 * wgt;
                    v1 = (h1 / (1.f + __expf(-h1))) * g1 * wgt;
                } else if (OSEL == 0) {
                    v0 += bias1[n0 + c];
                    v1 += bias1[n0 + c + 1];
                }
                if (OSEL == 1 || OSEL == 3) {              // bf16 hi/lo pair out
                    bf16 *oh = (OSEL == 1) ? s_ah : s_zh;
                    bf16 *ol = (OSEL == 1) ? s_al : s_zl;
                    bf16 h0b = __float2bfloat16(v0), h1b = __float2bfloat16(v1);
                    *(uint32_t*)(oh + rowoff + c) = pack_bf2(v0, v1);
                    *(uint32_t*)(ol + rowoff + c) =
                        pack_bf2(v0 - __bfloat162float(h0b), v1 - __bfloat162float(h1b));
                } else {
                    float* op = (OSEL == 0) ? Oarg : g_y;
                    *(float2*)(op + rowoff + c) = make_float2(v0, v1);
                }
            }
        }
    }
}

// ---------- combine ----------
__global__ void combine_kernel(const float* __restrict__ b2, float* __restrict__ out)
{
    int t = blockIdx.x;
    int d = threadIdx.x * 4;
    int e0 = g_se[t*2+0], e1 = g_se[t*2+1];
    int r0 = g_off[e0] + g_sp[t*2+0];
    int r1 = g_off[e1] + g_sp[t*2+1];
    float w0 = g_sw[t*2+0], w1 = g_sw[t*2+1];
    float4 y0 = *(const float4*)&g_y[(size_t)r0 * DIMD + d];
    float4 y1 = *(const float4*)&g_y[(size_t)r1 * DIMD + d];
    float4 a0 = *(const float4*)&b2[(size_t)e0 * DIMD + d];
    float4 a1 = *(const float4*)&b2[(size_t)e1 * DIMD + d];
    float4* o = (float4*)&out[(size_t)t * DIMD + d];
    float4 c = *o;
    c.x += y0.x + y1.x + w0 * a0.x + w1 * a1.x;
    c.y += y0.y + y1.y + w0 * a0.y + w1 * a1.y;
    c.z += y0.z + y1.z + w0 * a0.z + w1 * a1.z;
    c.w += y0.w + y1.w + w0 * a0.w + w1 * a1.w;
    *o = c;
}

// ---------- launch ----------
extern "C" void kernel_launch(void* const* d_in, const int* in_sizes, int n_in,
                              void* d_out, int out_size)
{
    const float* x   = (const float*)d_in[0];
    const float* gw  = (const float*)d_in[1];
    const float* gb  = (const float*)d_in[2];
    const float* w1  = (const float*)d_in[3];
    const float* b1  = (const float*)d_in[4];
    const float* w3  = (const float*)d_in[5];
    const float* b3  = (const float*)d_in[6];
    const float* w2  = (const float*)d_in[7];
    const float* b2  = (const float*)d_in[8];
    const float* sw1 = (const float*)d_in[9];
    const float* sb1 = (const float*)d_in[10];
    const float* sw3 = (const float*)d_in[11];
    const float* sb3 = (const float*)d_in[12];
    const float* sw2 = (const float*)d_in[13];
    const float* sb2 = (const float*)d_in[14];
    float* out = (float*)d_out;

    const int SM_D = 2 * 38912, SM_S = 2 * 29696;
    cudaFuncSetAttribute(hmma_gemm<true,  false, false, 0, 2, 3>, cudaFuncAttributeMaxDynamicSharedMemorySize, SM_D);
    cudaFuncSetAttribute(hmma_gemm<true,  true,  true,  0, 0, 1>, cudaFuncAttributeMaxDynamicSharedMemorySize, SM_D);
    cudaFuncSetAttribute(hmma_gemm<false, false, false, 2, 3, 0>, cudaFuncAttributeMaxDynamicSharedMemorySize, SM_S);
    cudaFuncSetAttribute(hmma_gemm<false, true,  false, 1, 1, 2>, cudaFuncAttributeMaxDynamicSharedMemorySize, SM_S);

    // one-time splits (per replay; deterministic)
    auto blk = [](size_t n) { return (unsigned)((n / 4 + 255) / 256); };
    split_kernel<0><<<blk((size_t)T_TOKENS*DIMD), 256>>>(x,  (size_t)T_TOKENS*DIMD/4);
    split_kernel<1><<<blk((size_t)NEXP*DIMD*INTER), 256>>>(w1, (size_t)NEXP*DIMD*INTER/4);
    split_kernel<2><<<blk((size_t)NEXP*DIMD*INTER), 256>>>(w3, (size_t)NEXP*DIMD*INTER/4);
    split_kernel<3><<<blk((size_t)NEXP*INTER*DIMD), 256>>>(w2, (size_t)NEXP*INTER*DIMD/4);
    split_kernel<4><<<blk((size_t)DIMD*SINTER), 256>>>(sw1, (size_t)DIMD*SINTER/4);
    split_kernel<5><<<blk((size_t)DIMD*SINTER), 256>>>(sw3, (size_t)DIMD*SINTER/4);
    split_kernel<6><<<blk((size_t)SINTER*DIMD), 256>>>(sw2, (size_t)SINTER*DIMD/4);

    reset_kernel<<<1, 32>>>();
    gate_kernel<<<T_TOKENS / 4, dim3(32, 4)>>>(x, gw, gb);
    scan_kernel<<<1, 1>>>();

    // shared expert
    hmma_gemm<true,  false, false, 0, 2, 3><<<dim3(SINTER/64, T_TOKENS/128), 256, SM_D>>>(
        sb1, sb3, nullptr, SINTER, DIMD);
    hmma_gemm<false, false, false, 2, 3, 0><<<dim3(DIMD/64, T_TOKENS/128), 256, SM_S>>>(
        sb2, nullptr, out, DIMD, SINTER);

    // routed experts
    hmma_gemm<true,  true,  true,  0, 0, 1><<<dim3(INTER/64, T_TOKENS/128, NEXP), 256, SM_D>>>(
        b1, b3, nullptr, INTER, DIMD);
    hmma_gemm<false, true,  false, 1, 1, 2><<<dim3(DIMD/64, T_TOKENS/128, NEXP), 256, SM_S>>>(
        nullptr, nullptr, nullptr, DIMD, INTER);

    combine_kernel<<<T_TOKENS, 256>>>(b2, out);
}

// round 8
// speedup vs baseline: 2.4255x; 1.0573x over previous
#include <cuda_runtime.h>
#include <cuda_bf16.h>
#include <math.h>
#include <stdint.h>

#define T_TOKENS 4096
#define DIMD     1024
#define INTER    1408
#define SINTER   2816
#define NEXP     16
typedef __nv_bfloat16 bf16;

__device__ int   g_cnt[NEXP];
__device__ int   g_off[NEXP];
__device__ int   g_tok[NEXP * T_TOKENS];
__device__ float g_wt [NEXP * T_TOKENS];
__device__ int   g_se [T_TOKENS * 2];
__device__ int   g_sp [T_TOKENS * 2];
__device__ float g_sw [T_TOKENS * 2];
__device__ float g_y  [T_TOKENS * 2 * DIMD];

__device__ bf16 s_xh [T_TOKENS * DIMD],      s_xl [T_TOKENS * DIMD];
__device__ bf16 s_w1h[NEXP * DIMD * INTER],  s_w1l[NEXP * DIMD * INTER];
__device__ bf16 s_w3h[NEXP * DIMD * INTER],  s_w3l[NEXP * DIMD * INTER];
__device__ bf16 s_w2h[NEXP * INTER * DIMD],  s_w2l[NEXP * INTER * DIMD];
__device__ bf16 s_u1h[DIMD * SINTER],        s_u1l[DIMD * SINTER];
__device__ bf16 s_u3h[DIMD * SINTER],        s_u3l[DIMD * SINTER];
__device__ bf16 s_u2h[SINTER * DIMD],        s_u2l[SINTER * DIMD];
__device__ bf16 s_ah [T_TOKENS * 2 * INTER], s_al [T_TOKENS * 2 * INTER];
__device__ bf16 s_zh [T_TOKENS * SINTER],    s_zl [T_TOKENS * SINTER];

__device__ __forceinline__ uint32_t smem_u32(const void* p) {
    uint32_t a;
    asm("{ .reg .u64 t; cvta.to.shared.u64 t, %1; cvt.u32.u64 %0, t; }" : "=r"(a) : "l"(p));
    return a;
}
#define LDSM_X4(R, a) \
    asm volatile("ldmatrix.sync.aligned.m8n8.x4.shared.b16 {%0,%1,%2,%3}, [%4];" \
        : "=r"((R)[0]), "=r"((R)[1]), "=r"((R)[2]), "=r"((R)[3]) : "r"(a))
#define LDSM_X4T(R, a) \
    asm volatile("ldmatrix.sync.aligned.m8n8.x4.trans.shared.b16 {%0,%1,%2,%3}, [%4];" \
        : "=r"((R)[0]), "=r"((R)[1]), "=r"((R)[2]), "=r"((R)[3]) : "r"(a))
#define MMA_BF16(C, A, b0, b1) \
    asm volatile("mma.sync.aligned.m16n8k16.row.col.f32.bf16.bf16.f32 " \
        "{%0,%1,%2,%3},{%4,%5,%6,%7},{%8,%9},{%0,%1,%2,%3};" \
        : "+f"((C)[0]), "+f"((C)[1]), "+f"((C)[2]), "+f"((C)[3]) \
        : "r"((A)[0]), "r"((A)[1]), "r"((A)[2]), "r"((A)[3]), "r"(b0), "r"(b1))
#define CP16(dst, src) \
    asm volatile("cp.async.cg.shared.global [%0], [%1], 16;" :: "r"(dst), "l"(src))
#define CPC()  asm volatile("cp.async.commit_group;")
#define CPW0() asm volatile("cp.async.wait_group 0;")
#define CPW1() asm volatile("cp.async.wait_group 1;")

__device__ __forceinline__ uint32_t pack_bf2(float a, float b) {
    __nv_bfloat162 t = __halves2bfloat162(__float2bfloat16(a), __float2bfloat16(b));
    return *(uint32_t*)&t;
}
__device__ __forceinline__ void split4(float4 v, bf16* h, bf16* l, size_t i) {
    bf16 h0 = __float2bfloat16(v.x), h1 = __float2bfloat16(v.y);
    bf16 h2 = __float2bfloat16(v.z), h3 = __float2bfloat16(v.w);
    uint2 H, L;
    H.x = pack_bf2(v.x, v.y); H.y = pack_bf2(v.z, v.w);
    L.x = pack_bf2(v.x - __bfloat162float(h0), v.y - __bfloat162float(h1));
    L.y = pack_bf2(v.z - __bfloat162float(h2), v.w - __bfloat162float(h3));
    *(uint2*)(h + i * 4) = H; *(uint2*)(l + i * 4) = L;
}

// ---------- splits ----------
#define N1 ((size_t)NEXP * DIMD * INTER / 4)
#define N2 ((size_t)DIMD * SINTER / 4)
__global__ void split_weights(const float* __restrict__ w1, const float* __restrict__ w3,
                              const float* __restrict__ w2, const float* __restrict__ u1,
                              const float* __restrict__ u3, const float* __restrict__ u2)
{
    size_t i = (size_t)blockIdx.x * blockDim.x + threadIdx.x;
    const float* src; bf16 *h, *l; size_t o;
    if      (i < N1)            { src = w1; h = s_w1h; l = s_w1l; o = i; }
    else if (i < 2*N1)          { src = w3; h = s_w3h; l = s_w3l; o = i - N1; }
    else if (i < 3*N1)          { src = w2; h = s_w2h; l = s_w2l; o = i - 2*N1; }
    else if (i < 3*N1 + N2)     { src = u1; h = s_u1h; l = s_u1l; o = i - 3*N1; }
    else if (i < 3*N1 + 2*N2)   { src = u3; h = s_u3h; l = s_u3l; o = i - 3*N1 - N2; }
    else if (i < 3*N1 + 3*N2)   { src = u2; h = s_u2h; l = s_u2l; o = i - 3*N1 - 2*N2; }
    else return;
    split4(*(const float4*)(src + o * 4), h, l, o);
}
__global__ void split_x(const float* __restrict__ x)
{
    size_t i = (size_t)blockIdx.x * blockDim.x + threadIdx.x;
    split4(*(const float4*)(x + i * 4), s_xh, s_xl, i);
}

// ---------- gate / scan ----------
__global__ void reset_kernel() { if (threadIdx.x < NEXP) g_cnt[threadIdx.x] = 0; }

__global__ void gate_kernel(const float* __restrict__ x, const float* __restrict__ gw,
                            const float* __restrict__ gb)
{
    int t = blockIdx.x * blockDim.y + threadIdx.y;
    if (t >= T_TOKENS) return;
    int lane = threadIdx.x;
    float acc[NEXP];
#pragma unroll
    for (int e = 0; e < NEXP; e++) acc[e] = 0.f;
    const float* xr = x + (size_t)t * DIMD;
    for (int d = lane; d < DIMD; d += 32) {
        float xv = xr[d];
        const float* g = gw + (size_t)d * NEXP;
#pragma unroll
        for (int e = 0; e < NEXP; e++) acc[e] += xv * g[e];
    }
#pragma unroll
    for (int e = 0; e < NEXP; e++)
#pragma unroll
        for (int o = 16; o > 0; o >>= 1) acc[e] += __shfl_xor_sync(0xffffffffu, acc[e], o);
    if (lane == 0) {
        float mx = -1e30f;
#pragma unroll
        for (int e = 0; e < NEXP; e++) { acc[e] += gb[e]; mx = fmaxf(mx, acc[e]); }
        float s = 0.f;
#pragma unroll
        for (int e = 0; e < NEXP; e++) { acc[e] = expf(acc[e] - mx); s += acc[e]; }
        int b0 = 0; float v0 = -1.f;
#pragma unroll
        for (int e = 0; e < NEXP; e++) if (acc[e] > v0) { v0 = acc[e]; b0 = e; }
        int b1i = -1; float v1 = -1.f;
#pragma unroll
        for (int e = 0; e < NEXP; e++) if (e != b0 && acc[e] > v1) { v1 = acc[e]; b1i = e; }
        float w0 = v0 / s, w1 = v1 / s;
        int p0 = atomicAdd(&g_cnt[b0], 1);
        g_tok[b0 * T_TOKENS + p0] = t;  g_wt[b0 * T_TOKENS + p0] = w0;
        int p1 = atomicAdd(&g_cnt[b1i], 1);
        g_tok[b1i * T_TOKENS + p1] = t; g_wt[b1i * T_TOKENS + p1] = w1;
        g_se[t*2+0] = b0;  g_sp[t*2+0] = p0;  g_sw[t*2+0] = w0;
        g_se[t*2+1] = b1i; g_sp[t*2+1] = p1;  g_sw[t*2+1] = w1;
    }
}

__global__ void scan_kernel() {
    int s = 0;
    for (int e = 0; e < NEXP; e++) { g_off[e] = s; s += g_cnt[e]; }
}

// ---------- UP: dual-B SwiGLU GEMM, z==NEXP -> shared slice. 2-stage, 2 CTAs/SM ----------
// Stage: AH 0 (128x80B) | AL 10240 | B1H 20480 (32x144B) | B1L 25088 | B2H 29696 | B2L 34304
__global__ void __launch_bounds__(256, 2)
up_gemm(const float* __restrict__ b1, const float* __restrict__ b3,
        const float* __restrict__ sb1, const float* __restrict__ sb3)
{
    extern __shared__ char smem[];
    const int z = blockIdx.z;
    const bool sh = (z == NEXP);
    if (!sh && blockIdx.x >= INTER / 64) return;
    const int NN = sh ? SINTER : INTER;
    const int n0 = blockIdx.x * 64, m0 = blockIdx.y * 128;
    int M = T_TOKENS, rowbase = 0;
    const int* rowidx = nullptr; const float* wv = nullptr;
    const bf16 *B1h, *B1l, *B2h, *B2l;
    const float *bias1, *bias2;
    bf16 *oh, *ol;
    if (sh) {
        B1h = s_u1h; B1l = s_u1l; B2h = s_u3h; B2l = s_u3l;
        bias1 = sb1; bias2 = sb3; oh = s_zh; ol = s_zl;
    } else {
        M = g_cnt[z];
        if (m0 >= M) return;
        rowbase = g_off[z];
        size_t wo = (size_t)z * DIMD * INTER;
        B1h = s_w1h + wo; B1l = s_w1l + wo; B2h = s_w3h + wo; B2l = s_w3l + wo;
        bias1 = b1 + (size_t)z * INTER; bias2 = b3 + (size_t)z * INTER;
        rowidx = g_tok + z * T_TOKENS; wv = g_wt + z * T_TOKENS;
        oh = s_ah; ol = s_al;
    }

    const int tid = threadIdx.x, lane = tid & 31, wid = tid >> 5;
    const int wm = wid >> 2, wn = wid & 3;
    const uint32_t sbase = smem_u32(smem);
    const int SSZ = 38912;
    const int KK = DIMD;

    const bf16 *apH[2], *apL[2];
    uint32_t adst[2];
#pragma unroll
    for (int it = 0; it < 2; it++) {
        int task = tid + it * 256, row = task >> 2, c = task & 3;
        int r = m0 + row; if (r >= M) r = M - 1;
        size_t ro = rowidx ? (size_t)rowidx[r] * KK : (size_t)r * KK;
        apH[it] = s_xh + ro + c * 8;
        apL[it] = s_xl + ro + c * 8;
        adst[it] = row * 80 + c * 16;
    }
    const int bkl = tid >> 3, bc = tid & 7;
    const size_t bbase = (size_t)bkl * NN + n0 + bc * 8;
    const uint32_t bdst = bkl * 144 + bc * 16;

    auto stage = [&](int k0, int st) {
        uint32_t sp = sbase + st * SSZ;
#pragma unroll
        for (int it = 0; it < 2; it++) {
            uint32_t d = sp + adst[it];
            CP16(d, apH[it] + k0);
            CP16(d + 10240, apL[it] + k0);
        }
        size_t go = bbase + (size_t)k0 * NN;
        uint32_t d = sp + 20480 + bdst;
        CP16(d, B1h + go);
        CP16(d + 4608, B1l + go);
        CP16(d + 9216,  B2h + go);
        CP16(d + 13824, B2l + go);
    };

    float accH[4][2][4], accG[4][2][4];
#pragma unroll
    for (int a = 0; a < 4; a++)
#pragma unroll
        for (int b = 0; b < 2; b++)
#pragma unroll
            for (int c = 0; c < 4; c++) { accH[a][b][c] = 0.f; accG[a][b][c] = 0.f; }

    const int NC = KK / 32;
    stage(0, 0); CPC();
#pragma unroll 1
    for (int i = 0; i < NC; i++) {
        CPW0();
        __syncthreads();
        if (i + 1 < NC) { stage((i + 1) * 32, (i + 1) & 1); CPC(); }
        uint32_t sb = sbase + (i & 1) * SSZ;
#pragma unroll
        for (int s = 0; s < 2; s++) {
            uint32_t bo = (uint32_t)(s * 16 + (lane & 15)) * 144
                        + wn * 32 + (lane >> 4) * 16;
            uint32_t b1h[4], b1l[4], b2h[4], b2l[4];
            LDSM_X4T(b1h, sb + 20480 + bo);
            LDSM_X4T(b1l, sb + 25088 + bo);
            LDSM_X4T(b2h, sb + 29696 + bo);
            LDSM_X4T(b2l, sb + 34304 + bo);
#pragma unroll
            for (int mt = 0; mt < 4; mt++) {
                uint32_t ah[4], al[4];
                uint32_t ro = (uint32_t)(wm * 64 + mt * 16 + (lane & 15)) * 80
                            + (lane >> 4) * 16 + s * 32;
                LDSM_X4(ah, sb + ro);
                LDSM_X4(al, sb + 10240 + ro);
#pragma unroll
                for (int nt = 0; nt < 2; nt++) {
                    MMA_BF16(accH[mt][nt], ah, b1h[nt*2], b1h[nt*2+1]);
                    MMA_BF16(accH[mt][nt], ah, b1l[nt*2], b1l[nt*2+1]);
                    MMA_BF16(accH[mt][nt], al, b1h[nt*2], b1h[nt*2+1]);
                    MMA_BF16(accG[mt][nt], ah, b2h[nt*2], b2h[nt*2+1]);
                    MMA_BF16(accG[mt][nt], ah, b2l[nt*2], b2l[nt*2+1]);
                    MMA_BF16(accG[mt][nt], al, b2h[nt*2], b2h[nt*2+1]);
                }
            }
        }
    }

#pragma unroll
    for (int mt = 0; mt < 4; mt++) {
        int rb = m0 + wm * 64 + mt * 16 + (lane >> 2);
#pragma unroll
        for (int h = 0; h < 2; h++) {
            int r = rb + h * 8;
            if (r >= M) continue;
            float wgt = sh ? 1.f : wv[r];
            size_t rowoff = (size_t)(rowbase + r) * NN + n0;
#pragma unroll
            for (int nt = 0; nt < 2; nt++) {
                int c = wn * 16 + nt * 8 + (lane & 3) * 2;
                float h0 = accH[mt][nt][h*2+0] + bias1[n0 + c];
                float h1 = accH[mt][nt][h*2+1] + bias1[n0 + c + 1];
                float g0 = accG[mt][nt][h*2+0] + bias2[n0 + c];
                float g1 = accG[mt][nt][h*2+1] + bias2[n0 + c + 1];
                float v0 = (h0 / (1.f + __expf(-h0))) * g0 * wgt;
                float v1 = (h1 / (1.f + __expf(-h1))) * g1 * wgt;
                bf16 t0 = __float2bfloat16(v0), t1 = __float2bfloat16(v1);
                *(uint32_t*)(oh + rowoff + c) = pack_bf2(v0, v1);
                *(uint32_t*)(ol + rowoff + c) =
                    pack_bf2(v0 - __bfloat162float(t0), v1 - __bfloat162float(t1));
            }
        }
    }
}

// ---------- DOWN: single-B GEMM, z==NEXP -> shared slice. 3-stage, 2 CTAs/SM ----------
// Stage: AH 0 (128x80B) | AL 10240 | BH 20480 (32x144B) | BL 25088   (29696 B)
__global__ void __launch_bounds__(256, 2)
down_gemm(const float* __restrict__ sb2, float* __restrict__ out)
{
    extern __shared__ char smem[];
    const int z = blockIdx.z;
    const bool sh = (z == NEXP);
    const int KK = sh ? SINTER : INTER;
    const int NN = DIMD;
    const int n0 = blockIdx.x * 64, m0 = blockIdx.y * 128;
    int M = T_TOKENS, rowbase = 0;
    const bf16 *Ah, *Al, *Bh, *Bl;
    if (sh) { Ah = s_zh; Al = s_zl; Bh = s_u2h; Bl = s_u2l; }
    else {
        M = g_cnt[z];
        if (m0 >= M) return;
        rowbase = g_off[z];
        size_t wo = (size_t)z * INTER * DIMD;
        Ah = s_ah; Al = s_al; Bh = s_w2h + wo; Bl = s_w2l + wo;
    }

    const int tid = threadIdx.x, lane = tid & 31, wid = tid >> 5;
    const int wm = wid >> 2, wn = wid & 3;
    const uint32_t sbase = smem_u32(smem);
    const int SSZ = 29696;

    const bf16 *apH[2], *apL[2];
    uint32_t adst[2];
#pragma unroll
    for (int it = 0; it < 2; it++) {
        int task = tid + it * 256, row = task >> 2, c = task & 3;
        int r = m0 + row; if (r >= M) r = M - 1;
        size_t ro = (size_t)(rowbase + r) * KK;
        apH[it] = Ah + ro + c * 8;
        apL[it] = Al + ro + c * 8;
        adst[it] = row * 80 + c * 16;
    }
    const int bkl = tid >> 3, bc = tid & 7;
    const size_t bbase = (size_t)bkl * NN + n0 + bc * 8;
    const uint32_t bdst = bkl * 144 + bc * 16;

    auto stage = [&](int k0, int st) {
        uint32_t sp = sbase + st * SSZ;
#pragma unroll
        for (int it = 0; it < 2; it++) {
            uint32_t d = sp + adst[it];
            CP16(d, apH[it] + k0);
            CP16(d + 10240, apL[it] + k0);
        }
        size_t go = bbase + (size_t)k0 * NN;
        uint32_t d = sp + 20480 + bdst;
        CP16(d, Bh + go);
        CP16(d + 4608, Bl + go);
    };

    float accH[4][2][4];
#pragma unroll
    for (int a = 0; a < 4; a++)
#pragma unroll
        for (int b = 0; b < 2; b++)
#pragma unroll
            for (int c = 0; c < 4; c++) accH[a][b][c] = 0.f;

    const int NC = KK / 32;
    stage(0, 0); CPC();
    stage(32, 1); CPC();
#pragma unroll 1
    for (int i = 0; i < NC; i++) {
        if (i + 2 < NC) CPW1(); else CPW0();
        __syncthreads();
        if (i + 2 < NC) { stage((i + 2) * 32, (i + 2) % 3); CPC(); }
        uint32_t sb = sbase + (i % 3) * SSZ;
#pragma unroll
        for (int s = 0; s < 2; s++) {
            uint32_t bo = (uint32_t)(s * 16 + (lane & 15)) * 144
                        + wn * 32 + (lane >> 4) * 16;
            uint32_t b1h[4], b1l[4];
            LDSM_X4T(b1h, sb + 20480 + bo);
            LDSM_X4T(b1l, sb + 25088 + bo);
#pragma unroll
            for (int mt = 0; mt < 4; mt++) {
                uint32_t ah[4], al[4];
                uint32_t ro = (uint32_t)(wm * 64 + mt * 16 + (lane & 15)) * 80
                            + (lane >> 4) * 16 + s * 32;
                LDSM_X4(ah, sb + ro);
                LDSM_X4(al, sb + 10240 + ro);
#pragma unroll
                for (int nt = 0; nt < 2; nt++) {
                    MMA_BF16(accH[mt][nt], ah, b1h[nt*2], b1h[nt*2+1]);
                    MMA_BF16(accH[mt][nt], ah, b1l[nt*2], b1l[nt*2+1]);
                    MMA_BF16(accH[mt][nt], al, b1h[nt*2], b1h[nt*2+1]);
                }
            }
        }
    }

#pragma unroll
    for (int mt = 0; mt < 4; mt++) {
        int rb = m0 + wm * 64 + mt * 16 + (lane >> 2);
#pragma unroll
        for (int h = 0; h < 2; h++) {
            int r = rb + h * 8;
            if (r >= M) continue;
            size_t rowoff = (size_t)(rowbase + r) * NN + n0;
#pragma unroll
            for (int nt = 0; nt < 2; nt++) {
                int c = wn * 16 + nt * 8 + (lane & 3) * 2;
                float v0 = accH[mt][nt][h*2+0];
                float v1 = accH[mt][nt][h*2+1];
                if (sh) {
                    v0 += sb2[n0 + c]; v1 += sb2[n0 + c + 1];
                    *(float2*)(out + rowoff + c) = make_float2(v0, v1);
                } else {
                    *(float2*)(g_y + rowoff + c) = make_float2(v0, v1);
                }
            }
        }
    }
}

// ---------- combine ----------
__global__ void combine_kernel(const float* __restrict__ b2, float* __restrict__ out)
{
    int t = blockIdx.x;
    int d = threadIdx.x * 4;
    int e0 = g_se[t*2+0], e1 = g_se[t*2+1];
    int r0 = g_off[e0] + g_sp[t*2+0];
    int r1 = g_off[e1] + g_sp[t*2+1];
    float w0 = g_sw[t*2+0], w1 = g_sw[t*2+1];
    float4 y0 = *(const float4*)&g_y[(size_t)r0 * DIMD + d];
    float4 y1 = *(const float4*)&g_y[(size_t)r1 * DIMD + d];
    float4 a0 = *(const float4*)&b2[(size_t)e0 * DIMD + d];
    float4 a1 = *(const float4*)&b2[(size_t)e1 * DIMD + d];
    float4* o = (float4*)&out[(size_t)t * DIMD + d];
    float4 c = *o;
    c.x += y0.x + y1.x + w0 * a0.x + w1 * a1.x;
    c.y += y0.y + y1.y + w0 * a0.y + w1 * a1.y;
    c.z += y0.z + y1.z + w0 * a0.z + w1 * a1.z;
    c.w += y0.w + y1.w + w0 * a0.w + w1 * a1.w;
    *o = c;
}

// ---------- launch ----------
extern "C" void kernel_launch(void* const* d_in, const int* in_sizes, int n_in,
                              void* d_out, int out_size)
{
    const float* x   = (const float*)d_in[0];
    const float* gw  = (const float*)d_in[1];
    const float* gb  = (const float*)d_in[2];
    const float* w1  = (const float*)d_in[3];
    const float* b1  = (const float*)d_in[4];
    const float* w3  = (const float*)d_in[5];
    const float* b3  = (const float*)d_in[6];
    const float* w2  = (const float*)d_in[7];
    const float* b2  = (const float*)d_in[8];
    const float* sw1 = (const float*)d_in[9];
    const float* sb1 = (const float*)d_in[10];
    const float* sw3 = (const float*)d_in[11];
    const float* sb3 = (const float*)d_in[12];
    const float* sw2 = (const float*)d_in[13];
    const float* sb2 = (const float*)d_in[14];
    float* out = (float*)d_out;

    const int SM_UP = 2 * 38912;   // 77824
    const int SM_DN = 3 * 29696;   // 89088
    cudaFuncSetAttribute(up_gemm,   cudaFuncAttributeMaxDynamicSharedMemorySize, SM_UP);
    cudaFuncSetAttribute(down_gemm, cudaFuncAttributeMaxDynamicSharedMemorySize, SM_DN);

    // launch order chosen so ncu -s 5 profiles up_gemm
    reset_kernel<<<1, 32>>>();                                    // 0
    gate_kernel<<<T_TOKENS / 4, dim3(32, 4)>>>(x, gw, gb);        // 1
    scan_kernel<<<1, 1>>>();                                      // 2
    size_t nw = 3 * N1 + 3 * N2;
    split_weights<<<(unsigned)((nw + 255) / 256), 256>>>(w1, w3, w2, sw1, sw3, sw2); // 3
    split_x<<<T_TOKENS * DIMD / 4 / 256, 256>>>(x);               // 4
    up_gemm<<<dim3(SINTER / 64, T_TOKENS / 128, NEXP + 1), 256, SM_UP>>>(b1, b3, sb1, sb3); // 5
    down_gemm<<<dim3(DIMD / 64, T_TOKENS / 128, NEXP + 1), 256, SM_DN>>>(sb2, out);         // 6
    combine_kernel<<<T_TOKENS, 256>>>(b2, out);                   // 7
}

// round 9
// speedup vs baseline: 3.4106x; 1.4061x over previous
#include <cuda_runtime.h>
#include <cuda_fp16.h>
#include <math.h>
#include <stdint.h>

#define T_TOKENS 4096
#define DIMD     1024
#define INTER    1408
#define SINTER   2816
#define NEXP     16

__device__ int   g_cnt[NEXP];
__device__ int   g_off[NEXP];
__device__ int   g_tok[NEXP * T_TOKENS];
__device__ float g_wt [NEXP * T_TOKENS];
__device__ int   g_se [T_TOKENS * 2];
__device__ int   g_sp [T_TOKENS * 2];
__device__ float g_sw [T_TOKENS * 2];
__device__ float g_y  [T_TOKENS * 2 * DIMD];

// fp16 storage: A-side single, B-side hi/lo split
__device__ __half s_x  [T_TOKENS * DIMD];
__device__ __half s_w1h[NEXP * DIMD * INTER],  s_w1l[NEXP * DIMD * INTER];
__device__ __half s_w3h[NEXP * DIMD * INTER],  s_w3l[NEXP * DIMD * INTER];
__device__ __half s_w2h[NEXP * INTER * DIMD],  s_w2l[NEXP * INTER * DIMD];
__device__ __half s_u1h[DIMD * SINTER],        s_u1l[DIMD * SINTER];
__device__ __half s_u3h[DIMD * SINTER],        s_u3l[DIMD * SINTER];
__device__ __half s_u2h[SINTER * DIMD],        s_u2l[SINTER * DIMD];
__device__ __half s_a  [T_TOKENS * 2 * INTER];
__device__ __half s_z  [T_TOKENS * SINTER];

__device__ __forceinline__ uint32_t smem_u32(const void* p) {
    uint32_t a;
    asm("{ .reg .u64 t; cvta.to.shared.u64 t, %1; cvt.u32.u64 %0, t; }" : "=r"(a) : "l"(p));
    return a;
}
#define LDSM_X4(R, a) \
    asm volatile("ldmatrix.sync.aligned.m8n8.x4.shared.b16 {%0,%1,%2,%3}, [%4];" \
        : "=r"((R)[0]), "=r"((R)[1]), "=r"((R)[2]), "=r"((R)[3]) : "r"(a))
#define LDSM_X4T(R, a) \
    asm volatile("ldmatrix.sync.aligned.m8n8.x4.trans.shared.b16 {%0,%1,%2,%3}, [%4];" \
        : "=r"((R)[0]), "=r"((R)[1]), "=r"((R)[2]), "=r"((R)[3]) : "r"(a))
#define MMA_F16(C, A, b0, b1) \
    asm volatile("mma.sync.aligned.m16n8k16.row.col.f32.f16.f16.f32 " \
        "{%0,%1,%2,%3},{%4,%5,%6,%7},{%8,%9},{%0,%1,%2,%3};" \
        : "+f"((C)[0]), "+f"((C)[1]), "+f"((C)[2]), "+f"((C)[3]) \
        : "r"((A)[0]), "r"((A)[1]), "r"((A)[2]), "r"((A)[3]), "r"(b0), "r"(b1))
#define CP16(dst, src) \
    asm volatile("cp.async.cg.shared.global [%0], [%1], 16;" :: "r"(dst), "l"(src))
#define CPC()  asm volatile("cp.async.commit_group;")
#define CPW0() asm volatile("cp.async.wait_group 0;")
#define CPW1() asm volatile("cp.async.wait_group 1;")

__device__ __forceinline__ uint32_t pack_h2(float a, float b) {
    __half2 t = __halves2half2(__float2half(a), __float2half(b));
    return *(uint32_t*)&t;
}

// ---------- splits ----------
#define N1 ((size_t)NEXP * DIMD * INTER / 4)
#define N2 ((size_t)DIMD * SINTER / 4)
__device__ __forceinline__ void split4(float4 v, __half* h, __half* l, size_t i) {
    __half h0 = __float2half(v.x), h1 = __float2half(v.y);
    __half h2 = __float2half(v.z), h3 = __float2half(v.w);
    uint2 H, L;
    H.x = pack_h2(v.x, v.y); H.y = pack_h2(v.z, v.w);
    L.x = pack_h2(v.x - __half2float(h0), v.y - __half2float(h1));
    L.y = pack_h2(v.z - __half2float(h2), v.w - __half2float(h3));
    *(uint2*)(h + i * 4) = H; *(uint2*)(l + i * 4) = L;
}
__global__ void split_weights(const float* __restrict__ w1, const float* __restrict__ w3,
                              const float* __restrict__ w2, const float* __restrict__ u1,
                              const float* __restrict__ u3, const float* __restrict__ u2)
{
    size_t i = (size_t)blockIdx.x * blockDim.x + threadIdx.x;
    const float* src; __half *h, *l; size_t o;
    if      (i < N1)          { src = w1; h = s_w1h; l = s_w1l; o = i; }
    else if (i < 2*N1)        { src = w3; h = s_w3h; l = s_w3l; o = i - N1; }
    else if (i < 3*N1)        { src = w2; h = s_w2h; l = s_w2l; o = i - 2*N1; }
    else if (i < 3*N1 + N2)   { src = u1; h = s_u1h; l = s_u1l; o = i - 3*N1; }
    else if (i < 3*N1 + 2*N2) { src = u3; h = s_u3h; l = s_u3l; o = i - 3*N1 - N2; }
    else if (i < 3*N1 + 3*N2) { src = u2; h = s_u2h; l = s_u2l; o = i - 3*N1 - 2*N2; }
    else return;
    split4(*(const float4*)(src + o * 4), h, l, o);
}
__global__ void split_x(const float* __restrict__ x)
{
    size_t i = (size_t)blockIdx.x * blockDim.x + threadIdx.x;
    float4 v = *(const float4*)(x + i * 4);
    uint2 H;
    H.x = pack_h2(v.x, v.y); H.y = pack_h2(v.z, v.w);
    *(uint2*)(s_x + i * 4) = H;
}

// ---------- gate / scan ----------
__global__ void reset_kernel() { if (threadIdx.x < NEXP) g_cnt[threadIdx.x] = 0; }

__global__ void gate_kernel(const float* __restrict__ x, const float* __restrict__ gw,
                            const float* __restrict__ gb)
{
    int t = blockIdx.x * blockDim.y + threadIdx.y;
    if (t >= T_TOKENS) return;
    int lane = threadIdx.x;
    float acc[NEXP];
#pragma unroll
    for (int e = 0; e < NEXP; e++) acc[e] = 0.f;
    const float* xr = x + (size_t)t * DIMD;
    for (int d = lane; d < DIMD; d += 32) {
        float xv = xr[d];
        const float* g = gw + (size_t)d * NEXP;
#pragma unroll
        for (int e = 0; e < NEXP; e++) acc[e] += xv * g[e];
    }
#pragma unroll
    for (int e = 0; e < NEXP; e++)
#pragma unroll
        for (int o = 16; o > 0; o >>= 1) acc[e] += __shfl_xor_sync(0xffffffffu, acc[e], o);
    if (lane == 0) {
        float mx = -1e30f;
#pragma unroll
        for (int e = 0; e < NEXP; e++) { acc[e] += gb[e]; mx = fmaxf(mx, acc[e]); }
        float s = 0.f;
#pragma unroll
        for (int e = 0; e < NEXP; e++) { acc[e] = expf(acc[e] - mx); s += acc[e]; }
        int b0 = 0; float v0 = -1.f;
#pragma unroll
        for (int e = 0; e < NEXP; e++) if (acc[e] > v0) { v0 = acc[e]; b0 = e; }
        int b1i = -1; float v1 = -1.f;
#pragma unroll
        for (int e = 0; e < NEXP; e++) if (e != b0 && acc[e] > v1) { v1 = acc[e]; b1i = e; }
        float w0 = v0 / s, w1 = v1 / s;
        int p0 = atomicAdd(&g_cnt[b0], 1);
        g_tok[b0 * T_TOKENS + p0] = t;  g_wt[b0 * T_TOKENS + p0] = w0;
        int p1 = atomicAdd(&g_cnt[b1i], 1);
        g_tok[b1i * T_TOKENS + p1] = t; g_wt[b1i * T_TOKENS + p1] = w1;
        g_se[t*2+0] = b0;  g_sp[t*2+0] = p0;  g_sw[t*2+0] = w0;
        g_se[t*2+1] = b1i; g_sp[t*2+1] = p1;  g_sw[t*2+1] = w1;
    }
}

__global__ void scan_kernel() {
    int s = 0;
    for (int e = 0; e < NEXP; e++) { g_off[e] = s; s += g_cnt[e]; }
}

// ---------- UP: dual-B SwiGLU GEMM (fp16, A single + B hi/lo). 3-stage, 2 CTAs/SM ----------
// Stage (28672 B): A 0 (128x80B) | B1H 10240 (32x144B) | B1L 14848 | B2H 19456 | B2L 24064
__global__ void __launch_bounds__(256, 2)
up_gemm(const float* __restrict__ b1, const float* __restrict__ b3,
        const float* __restrict__ sb1, const float* __restrict__ sb3)
{
    extern __shared__ char smem[];
    const int z = blockIdx.z;
    const bool sh = (z == NEXP);
    if (!sh && blockIdx.x >= INTER / 64) return;
    const int NN = sh ? SINTER : INTER;
    const int n0 = blockIdx.x * 64, m0 = blockIdx.y * 128;
    int M = T_TOKENS, rowbase = 0;
    const int* rowidx = nullptr; const float* wv = nullptr;
    const __half *B1h, *B1l, *B2h, *B2l;
    const float *bias1, *bias2;
    __half* oa;
    if (sh) {
        B1h = s_u1h; B1l = s_u1l; B2h = s_u3h; B2l = s_u3l;
        bias1 = sb1; bias2 = sb3; oa = s_z;
    } else {
        M = g_cnt[z];
        if (m0 >= M) return;
        rowbase = g_off[z];
        size_t wo = (size_t)z * DIMD * INTER;
        B1h = s_w1h + wo; B1l = s_w1l + wo; B2h = s_w3h + wo; B2l = s_w3l + wo;
        bias1 = b1 + (size_t)z * INTER; bias2 = b3 + (size_t)z * INTER;
        rowidx = g_tok + z * T_TOKENS; wv = g_wt + z * T_TOKENS;
        oa = s_a;
    }

    const int tid = threadIdx.x, lane = tid & 31, wid = tid >> 5;
    const int wm = wid >> 2, wn = wid & 3;
    const uint32_t sbase = smem_u32(smem);
    const int SSZ = 28672;
    const int KK = DIMD;

    const __half* ap[2];
    uint32_t adst[2];
#pragma unroll
    for (int it = 0; it < 2; it++) {
        int task = tid + it * 256, row = task >> 2, c = task & 3;
        int r = m0 + row; if (r >= M) r = M - 1;
        size_t ro = rowidx ? (size_t)rowidx[r] * KK : (size_t)r * KK;
        ap[it] = s_x + ro + c * 8;
        adst[it] = row * 80 + c * 16;
    }
    const int bkl = tid >> 3, bc = tid & 7;
    const size_t bbase = (size_t)bkl * NN + n0 + bc * 8;
    const uint32_t bdst = bkl * 144 + bc * 16;

    auto stage = [&](int k0, int st) {
        uint32_t sp = sbase + st * SSZ;
#pragma unroll
        for (int it = 0; it < 2; it++)
            CP16(sp + adst[it], ap[it] + k0);
        size_t go = bbase + (size_t)k0 * NN;
        uint32_t d = sp + 10240 + bdst;
        CP16(d,         B1h + go);
        CP16(d + 4608,  B1l + go);
        CP16(d + 9216,  B2h + go);
        CP16(d + 13824, B2l + go);
    };

    float accH[4][2][4], accG[4][2][4];
#pragma unroll
    for (int a = 0; a < 4; a++)
#pragma unroll
        for (int b = 0; b < 2; b++)
#pragma unroll
            for (int c = 0; c < 4; c++) { accH[a][b][c] = 0.f; accG[a][b][c] = 0.f; }

    const int NC = KK / 32;
    stage(0, 0); CPC();
    stage(32, 1); CPC();
#pragma unroll 1
    for (int i = 0; i < NC; i++) {
        if (i + 2 < NC) CPW1(); else CPW0();
        __syncthreads();
        if (i + 2 < NC) { stage((i + 2) * 32, (i + 2) % 3); CPC(); }
        uint32_t sb = sbase + (i % 3) * SSZ;
#pragma unroll
        for (int s = 0; s < 2; s++) {
            uint32_t bo = (uint32_t)(s * 16 + (lane & 15)) * 144
                        + wn * 32 + (lane >> 4) * 16;
            uint32_t b1h[4], b1l[4], b2h[4], b2l[4];
            LDSM_X4T(b1h, sb + 10240 + bo);
            LDSM_X4T(b1l, sb + 14848 + bo);
            LDSM_X4T(b2h, sb + 19456 + bo);
            LDSM_X4T(b2l, sb + 24064 + bo);
#pragma unroll
            for (int mt = 0; mt < 4; mt++) {
                uint32_t ah[4];
                uint32_t ro = (uint32_t)(wm * 64 + mt * 16 + (lane & 15)) * 80
                            + (lane >> 4) * 16 + s * 32;
                LDSM_X4(ah, sb + ro);
#pragma unroll
                for (int nt = 0; nt < 2; nt++) {
                    MMA_F16(accH[mt][nt], ah, b1h[nt*2], b1h[nt*2+1]);
                    MMA_F16(accH[mt][nt], ah, b1l[nt*2], b1l[nt*2+1]);
                    MMA_F16(accG[mt][nt], ah, b2h[nt*2], b2h[nt*2+1]);
                    MMA_F16(accG[mt][nt], ah, b2l[nt*2], b2l[nt*2+1]);
                }
            }
        }
    }

#pragma unroll
    for (int mt = 0; mt < 4; mt++) {
        int rb = m0 + wm * 64 + mt * 16 + (lane >> 2);
#pragma unroll
        for (int h = 0; h < 2; h++) {
            int r = rb + h * 8;
            if (r >= M) continue;
            float wgt = sh ? 1.f : wv[r];
            size_t rowoff = (size_t)(rowbase + r) * NN + n0;
#pragma unroll
            for (int nt = 0; nt < 2; nt++) {
                int c = wn * 16 + nt * 8 + (lane & 3) * 2;
                float h0 = accH[mt][nt][h*2+0] + bias1[n0 + c];
                float h1 = accH[mt][nt][h*2+1] + bias1[n0 + c + 1];
                float g0 = accG[mt][nt][h*2+0] + bias2[n0 + c];
                float g1 = accG[mt][nt][h*2+1] + bias2[n0 + c + 1];
                float v0 = (h0 / (1.f + __expf(-h0))) * g0 * wgt;
                float v1 = (h1 / (1.f + __expf(-h1))) * g1 * wgt;
                *(uint32_t*)(oa + rowoff + c) = pack_h2(v0, v1);
            }
        }
    }
}

// ---------- DOWN: single-B GEMM (fp16, A single + B hi/lo). 3-stage, 2 CTAs/SM ----------
// Stage (19456 B): A 0 (128x80B) | BH 10240 (32x144B) | BL 14848
__global__ void __launch_bounds__(256, 2)
down_gemm(const float* __restrict__ sb2, float* __restrict__ out)
{
    extern __shared__ char smem[];
    const int z = blockIdx.z;
    const bool sh = (z == NEXP);
    const int KK = sh ? SINTER : INTER;
    const int NN = DIMD;
    const int n0 = blockIdx.x * 64, m0 = blockIdx.y * 128;
    int M = T_TOKENS, rowbase = 0;
    const __half *Aa, *Bh, *Bl;
    if (sh) { Aa = s_z; Bh = s_u2h; Bl = s_u2l; }
    else {
        M = g_cnt[z];
        if (m0 >= M) return;
        rowbase = g_off[z];
        size_t wo = (size_t)z * INTER * DIMD;
        Aa = s_a; Bh = s_w2h + wo; Bl = s_w2l + wo;
    }

    const int tid = threadIdx.x, lane = tid & 31, wid = tid >> 5;
    const int wm = wid >> 2, wn = wid & 3;
    const uint32_t sbase = smem_u32(smem);
    const int SSZ = 19456;

    const __half* ap[2];
    uint32_t adst[2];
#pragma unroll
    for (int it = 0; it < 2; it++) {
        int task = tid + it * 256, row = task >> 2, c = task & 3;
        int r = m0 + row; if (r >= M) r = M - 1;
        ap[it] = Aa + (size_t)(rowbase + r) * KK + c * 8;
        adst[it] = row * 80 + c * 16;
    }
    const int bkl = tid >> 3, bc = tid & 7;
    const size_t bbase = (size_t)bkl * NN + n0 + bc * 8;
    const uint32_t bdst = bkl * 144 + bc * 16;

    auto stage = [&](int k0, int st) {
        uint32_t sp = sbase + st * SSZ;
#pragma unroll
        for (int it = 0; it < 2; it++)
            CP16(sp + adst[it], ap[it] + k0);
        size_t go = bbase + (size_t)k0 * NN;
        uint32_t d = sp + 10240 + bdst;
        CP16(d,        Bh + go);
        CP16(d + 4608, Bl + go);
    };

    float accH[4][2][4];
#pragma unroll
    for (int a = 0; a < 4; a++)
#pragma unroll
        for (int b = 0; b < 2; b++)
#pragma unroll
            for (int c = 0; c < 4; c++) accH[a][b][c] = 0.f;

    const int NC = KK / 32;
    stage(0, 0); CPC();
    stage(32, 1); CPC();
#pragma unroll 1
    for (int i = 0; i < NC; i++) {
        if (i + 2 < NC) CPW1(); else CPW0();
        __syncthreads();
        if (i + 2 < NC) { stage((i + 2) * 32, (i + 2) % 3); CPC(); }
        uint32_t sb = sbase + (i % 3) * SSZ;
#pragma unroll
        for (int s = 0; s < 2; s++) {
            uint32_t bo = (uint32_t)(s * 16 + (lane & 15)) * 144
                        + wn * 32 + (lane >> 4) * 16;
            uint32_t b1h[4], b1l[4];
            LDSM_X4T(b1h, sb + 10240 + bo);
            LDSM_X4T(b1l, sb + 14848 + bo);
#pragma unroll
            for (int mt = 0; mt < 4; mt++) {
                uint32_t ah[4];
                uint32_t ro = (uint32_t)(wm * 64 + mt * 16 + (lane & 15)) * 80
                            + (lane >> 4) * 16 + s * 32;
                LDSM_X4(ah, sb + ro);
#pragma unroll
                for (int nt = 0; nt < 2; nt++) {
                    MMA_F16(accH[mt][nt], ah, b1h[nt*2], b1h[nt*2+1]);
                    MMA_F16(accH[mt][nt], ah, b1l[nt*2], b1l[nt*2+1]);
                }
            }
        }
    }

#pragma unroll
    for (int mt = 0; mt < 4; mt++) {
        int rb = m0 + wm * 64 + mt * 16 + (lane >> 2);
#pragma unroll
        for (int h = 0; h < 2; h++) {
            int r = rb + h * 8;
            if (r >= M) continue;
            size_t rowoff = (size_t)(rowbase + r) * NN + n0;
#pragma unroll
            for (int nt = 0; nt < 2; nt++) {
                int c = wn * 16 + nt * 8 + (lane & 3) * 2;
                float v0 = accH[mt][nt][h*2+0];
                float v1 = accH[mt][nt][h*2+1];
                if (sh) {
                    v0 += sb2[n0 + c]; v1 += sb2[n0 + c + 1];
                    *(float2*)(out + rowoff + c) = make_float2(v0, v1);
                } else {
                    *(float2*)(g_y + rowoff + c) = make_float2(v0, v1);
                }
            }
        }
    }
}

// ---------- combine ----------
__global__ void combine_kernel(const float* __restrict__ b2, float* __restrict__ out)
{
    int t = blockIdx.x;
    int d = threadIdx.x * 4;
    int e0 = g_se[t*2+0], e1 = g_se[t*2+1];
    int r0 = g_off[e0] + g_sp[t*2+0];
    int r1 = g_off[e1] + g_sp[t*2+1];
    float w0 = g_sw[t*2+0], w1 = g_sw[t*2+1];
    float4 y0 = *(const float4*)&g_y[(size_t)r0 * DIMD + d];
    float4 y1 = *(const float4*)&g_y[(size_t)r1 * DIMD + d];
    float4 a0 = *(const float4*)&b2[(size_t)e0 * DIMD + d];
    float4 a1 = *(const float4*)&b2[(size_t)e1 * DIMD + d];
    float4* o = (float4*)&out[(size_t)t * DIMD + d];
    float4 c = *o;
    c.x += y0.x + y1.x + w0 * a0.x + w1 * a1.x;
    c.y += y0.y + y1.y + w0 * a0.y + w1 * a1.y;
    c.z += y0.z + y1.z + w0 * a0.z + w1 * a1.z;
    c.w += y0.w + y1.w + w0 * a0.w + w1 * a1.w;
    *o = c;
}

// ---------- launch ----------
extern "C" void kernel_launch(void* const* d_in, const int* in_sizes, int n_in,
                              void* d_out, int out_size)
{
    const float* x   = (const float*)d_in[0];
    const float* gw  = (const float*)d_in[1];
    const float* gb  = (const float*)d_in[2];
    const float* w1  = (const float*)d_in[3];
    const float* b1  = (const float*)d_in[4];
    const float* w3  = (const float*)d_in[5];
    const float* b3  = (const float*)d_in[6];
    const float* w2  = (const float*)d_in[7];
    const float* b2  = (const float*)d_in[8];
    const float* sw1 = (const float*)d_in[9];
    const float* sb1 = (const float*)d_in[10];
    const float* sw3 = (const float*)d_in[11];
    const float* sb3 = (const float*)d_in[12];
    const float* sw2 = (const float*)d_in[13];
    const float* sb2 = (const float*)d_in[14];
    float* out = (float*)d_out;

    const int SM_UP = 3 * 28672;   // 86016 (x2 CTAs = 172032 <= 228KB)
    const int SM_DN = 3 * 19456;   // 58368
    cudaFuncSetAttribute(up_gemm,   cudaFuncAttributeMaxDynamicSharedMemorySize, SM_UP);
    cudaFuncSetAttribute(down_gemm, cudaFuncAttributeMaxDynamicSharedMemorySize, SM_DN);

    reset_kernel<<<1, 32>>>();
    gate_kernel<<<T_TOKENS / 4, dim3(32, 4)>>>(x, gw, gb);
    scan_kernel<<<1, 1>>>();
    size_t nw = 3 * N1 + 3 * N2;
    split_weights<<<(unsigned)((nw + 255) / 256), 256>>>(w1, w3, w2, sw1, sw3, sw2);
    split_x<<<T_TOKENS * DIMD / 4 / 256, 256>>>(x);
    up_gemm<<<dim3(SINTER / 64, T_TOKENS / 128, NEXP + 1), 256, SM_UP>>>(b1, b3, sb1, sb3);
    down_gemm<<<dim3(DIMD / 64, T_TOKENS / 128, NEXP + 1), 256, SM_DN>>>(sb2, out);
    combine_kernel<<<T_TOKENS, 256>>>(b2, out);
}